// round 6
// baseline (speedup 1.0000x reference)
#include <cuda_runtime.h>
#include <cuda_bf16.h>
#include <cstddef>
#include <cstdint>

// ---------------- problem constants ----------------
#define BQ     4
#define DMODEL 1024
#define LSEQ   2048
#define DINNER 2048
#define DSTATE 16
#define DTRANK 64
#define BL     8192
#define XPN    96

// plane sizes (elements)
#define SZ_W1 ((size_t)4096 * 1024)
#define SZ_WX ((size_t)96 * 2048)
#define SZ_WD ((size_t)2048 * 64)
#define SZ_WO ((size_t)1024 * 2048)
#define SZ_WP ((size_t)1024 * 1024)
#define SZ_XT ((size_t)BL * 1024)
#define SZ_UC ((size_t)BL * 2048)
#define SZ_XD ((size_t)BL * 96)
#define SZ_Y  ((size_t)BL * 2048)
#define SZ_O1 ((size_t)BL * 1024)

// ---------------- scratch: hi plane at [0,N), lo plane at [N,2N) ----------------
__device__ __nv_bfloat16 g_w1b[2 * SZ_W1];
__device__ __nv_bfloat16 g_wxb[2 * SZ_WX];
__device__ __nv_bfloat16 g_wdb[2 * SZ_WD];
__device__ __nv_bfloat16 g_wob[2 * SZ_WO];
__device__ __nv_bfloat16 g_wpb[2 * SZ_WP];
__device__ __nv_bfloat16 g_xTb[2 * SZ_XT];
__device__ __nv_bfloat16 g_ucb[2 * SZ_UC];
__device__ __nv_bfloat16 g_xdb[2 * SZ_XD];
__device__ __nv_bfloat16 g_yb [2 * SZ_Y];
__device__ __nv_bfloat16 g_o1b[2 * SZ_O1];
__device__ float g_xz   [(size_t)BL * 4096];
__device__ float g_ucf  [(size_t)BL * 2048];
__device__ float g_xdf  [(size_t)BL * 96];
__device__ float g_delta[(size_t)BL * 2048];

__device__ __forceinline__ float softplusf(float x) {
    return (x > 20.f) ? x : log1pf(__expf(x));
}
__device__ __forceinline__ float siluf(float x) {
    return x / (1.f + __expf(-x));
}
__device__ __forceinline__ uint32_t smem_u32(const void* p) {
    uint32_t a;
    asm("{ .reg .u64 t; cvta.to.shared.u64 t, %1; cvt.u32.u64 %0, t; }" : "=r"(a) : "l"(p));
    return a;
}

#define MMA_BF16(d, a, b0v, b1v) \
    asm volatile("mma.sync.aligned.m16n8k16.row.col.f32.bf16.bf16.f32 " \
        "{%0,%1,%2,%3}, {%4,%5,%6,%7}, {%8,%9}, {%0,%1,%2,%3};" \
        : "+f"((d)[0]), "+f"((d)[1]), "+f"((d)[2]), "+f"((d)[3]) \
        : "r"((a)[0]), "r"((a)[1]), "r"((a)[2]), "r"((a)[3]), "r"(b0v), "r"(b1v))

#define LDSM4(r, addr) \
    asm volatile("ldmatrix.sync.aligned.m8n8.x4.shared.b16 {%0,%1,%2,%3}, [%4];" \
        : "=r"((r)[0]), "=r"((r)[1]), "=r"((r)[2]), "=r"((r)[3]) : "r"(addr))

#define CP_ASYNC(dst, src) \
    asm volatile("cp.async.cg.shared.global [%0], [%1], 16;" :: "r"(dst), "l"(src) : "memory")
#define CP_ASYNC_Z(dst, src, sz) \
    asm volatile("cp.async.cg.shared.global [%0], [%1], 16, %2;" :: "r"(dst), "l"(src), "r"(sz) : "memory")
#define CP_COMMIT()  asm volatile("cp.async.commit_group;" ::: "memory")
#define CP_WAIT1()   asm volatile("cp.async.wait_group 1;" ::: "memory")

// tile: 128 rows x 64B, XOR swizzle on 16B chunks
__device__ __forceinline__ uint32_t swz(int row, int cc) {
    uint32_t o = (uint32_t)(row * 64 + cc * 16);
    return o ^ ((((uint32_t)row >> 1) & 7u) << 4);
}

#define STAGE_SZ 32768
#define GEMM_SMEM (3 * STAGE_SZ)   // 98304

// ---------------- fp32 -> bf16 hi/lo converter ----------------
__global__ void cvt_k(const float* __restrict__ src, __nv_bfloat16* __restrict__ db, size_t n) {
    size_t i = (size_t)blockIdx.x * 256 + threadIdx.x;
    float4 v = *((const float4*)src + i);
    __nv_bfloat162 h0 = __floats2bfloat162_rn(v.x, v.y);
    __nv_bfloat162 h1 = __floats2bfloat162_rn(v.z, v.w);
    __nv_bfloat162 l0 = __floats2bfloat162_rn(v.x - __bfloat162float(h0.x),
                                              v.y - __bfloat162float(h0.y));
    __nv_bfloat162 l1 = __floats2bfloat162_rn(v.z - __bfloat162float(h1.x),
                                              v.w - __bfloat162float(h1.y));
    ((__nv_bfloat162*)db)[2 * i]     = h0;
    ((__nv_bfloat162*)db)[2 * i + 1] = h1;
    ((__nv_bfloat162*)(db + n))[2 * i]     = l0;
    ((__nv_bfloat162*)(db + n))[2 * i + 1] = l1;
}

// ---------------- x transpose -> hi/lo planes ----------------
__global__ void transpose_k(const float* __restrict__ x) {
    __shared__ float t[32][33];
    int b = blockIdx.z;
    int l0 = blockIdx.x * 32, k0 = blockIdx.y * 32;
    int tx = threadIdx.x, ty = threadIdx.y;
#pragma unroll
    for (int i = 0; i < 4; i++)
        t[ty + 8 * i][tx] = x[((size_t)(b * DMODEL + k0 + ty + 8 * i)) * LSEQ + l0 + tx];
    __syncthreads();
#pragma unroll
    for (int i = 0; i < 4; i++) {
        float v = t[tx][ty + 8 * i];
        size_t o = ((size_t)(b * LSEQ + l0 + ty + 8 * i)) * DMODEL + k0 + tx;
        __nv_bfloat16 h = __float2bfloat16(v);
        g_xTb[o] = h;
        g_xTb[SZ_XT + o] = __float2bfloat16(v - __bfloat162float(h));
    }
}

// ---------------- bf16x3 GEMM with cp.async + ldmatrix ----------------
// C[M,N] = A[M,K] @ W[N,K]^T ; A,W given as hi/lo bf16 planes.
// EPI: 0 fp32 | 1 softplus+bias fp32 | 2 transposed+bias fp32 | 3 fp32 + hi/lo | 4 hi/lo only
template<int EPI>
__global__ void __launch_bounds__(256, 2)
hgemm(const __nv_bfloat16* __restrict__ Ah, const __nv_bfloat16* __restrict__ Al,
      const __nv_bfloat16* __restrict__ Bh, const __nv_bfloat16* __restrict__ Bl,
      const float* __restrict__ bias, float* __restrict__ C,
      __nv_bfloat16* __restrict__ Ch, __nv_bfloat16* __restrict__ Cl,
      int M, int N, int K, int lda, int ldc)
{
    extern __shared__ char smem[];
    const uint32_t sb = smem_u32(smem);
    const int tid = threadIdx.x, lane = tid & 31, wid = tid >> 5;
    const int wm = wid >> 1, wn = wid & 1;
    const int bm = blockIdx.y * 128, bn = blockIdx.x * 128;
    const int nc = K >> 5;

    // ldmatrix lane bases (A tiles): row = wm*32 + i*16 + (lane&15), khalf = lane>>4
    const int ar0 = wm * 32 + (lane & 15);
    const uint32_t akh = (uint32_t)(lane >> 4) << 4;
    const uint32_t ab0 = swz(ar0, 0) ^ akh;
    const uint32_t ab1 = swz(ar0 + 16, 0) ^ akh;
    const int brlane = wn * 64 + (lane & 15);

    float acc[2][8][4];
#pragma unroll
    for (int i = 0; i < 2; i++)
#pragma unroll
        for (int j = 0; j < 8; j++)
#pragma unroll
            for (int t = 0; t < 4; t++) acc[i][j][t] = 0.f;

    auto issue = [&](int chunk, int s) {
        const uint32_t stage = sb + s * STAGE_SZ;
        const int k0 = chunk * 32;
#pragma unroll
        for (int q = 0; q < 8; q++) {
            int c  = q * 256 + tid;
            int tl = c >> 9, r = (c >> 2) & 127, cc = c & 3;
            uint32_t so = stage + tl * 8192 + swz(r, cc);
            if (tl < 2) {
                const __nv_bfloat16* src = (tl == 0 ? Ah : Al)
                    + (size_t)(bm + r) * lda + k0 + cc * 8;
                CP_ASYNC(so, src);
            } else {
                int n = bn + r;
                int ok = (n < N);
                const __nv_bfloat16* src = (tl == 2 ? Bh : Bl)
                    + (size_t)(ok ? n : 0) * K + k0 + cc * 8;
                CP_ASYNC_Z(so, src, ok ? 16 : 0);
            }
        }
    };

    issue(0, 0); CP_COMMIT();
    if (nc > 1) issue(1, 1);
    CP_COMMIT();

    for (int c = 0; c < nc; c++) {
        const int s = c % 3;
        CP_WAIT1();
        __syncthreads();
        if (c + 2 < nc) issue(c + 2, (c + 2) % 3);
        CP_COMMIT();

        const uint32_t st = sb + s * STAGE_SZ;
#pragma unroll
        for (int ks = 0; ks < 2; ks++) {
            const uint32_t kx = (uint32_t)ks << 5;
            uint32_t ah0[4], ah1[4], al0[4], al1[4];
            LDSM4(ah0, st + (ab0 ^ kx));
            LDSM4(ah1, st + (ab1 ^ kx));
            LDSM4(al0, st + 8192 + (ab0 ^ kx));
            LDSM4(al1, st + 8192 + (ab1 ^ kx));
#pragma unroll
            for (int g = 0; g < 4; g++) {
                const int br = brlane + g * 16;
                const uint32_t bo = swz(br, 0) ^ akh ^ kx;
                uint32_t bh[4], blo[4];
                LDSM4(bh,  st + 16384 + bo);
                LDSM4(blo, st + 24576 + bo);
                const int j0 = g * 2, j1 = g * 2 + 1;
                MMA_BF16(acc[0][j0], ah0, bh[0], bh[2]);
                MMA_BF16(acc[1][j0], ah1, bh[0], bh[2]);
                MMA_BF16(acc[0][j1], ah0, bh[1], bh[3]);
                MMA_BF16(acc[1][j1], ah1, bh[1], bh[3]);
                MMA_BF16(acc[0][j0], ah0, blo[0], blo[2]);
                MMA_BF16(acc[1][j0], ah1, blo[0], blo[2]);
                MMA_BF16(acc[0][j1], ah0, blo[1], blo[3]);
                MMA_BF16(acc[1][j1], ah1, blo[1], blo[3]);
                MMA_BF16(acc[0][j0], al0, bh[0], bh[2]);
                MMA_BF16(acc[1][j0], al1, bh[0], bh[2]);
                MMA_BF16(acc[0][j1], al0, bh[1], bh[3]);
                MMA_BF16(acc[1][j1], al1, bh[1], bh[3]);
            }
        }
        __syncthreads();
    }

    // ---------------- epilogue ----------------
    const int lr = lane >> 2, lc = lane & 3;
#pragma unroll
    for (int i = 0; i < 2; i++) {
#pragma unroll
        for (int j = 0; j < 8; j++) {
            int r0 = bm + wm * 32 + i * 16 + lr;
            int cn = bn + wn * 64 + j * 8 + lc * 2;
            if (cn >= N) continue;
            float c0 = acc[i][j][0], c1 = acc[i][j][1];
            float c2 = acc[i][j][2], c3 = acc[i][j][3];
            if (EPI == 0) {
                *(float2*)&C[(size_t)r0 * ldc + cn]       = make_float2(c0, c1);
                *(float2*)&C[(size_t)(r0 + 8) * ldc + cn] = make_float2(c2, c3);
            } else if (EPI == 1) {
                float b0 = bias[cn], b1 = bias[cn + 1];
                *(float2*)&C[(size_t)r0 * ldc + cn] =
                    make_float2(softplusf(c0 + b0), softplusf(c1 + b1));
                *(float2*)&C[(size_t)(r0 + 8) * ldc + cn] =
                    make_float2(softplusf(c2 + b0), softplusf(c3 + b1));
            } else if (EPI == 2) {
                float b0 = bias[cn], b1 = bias[cn + 1];
                int bb = r0 >> 11, l0 = r0 & (LSEQ - 1);
                size_t base0 = ((size_t)(bb * DMODEL + cn)) * LSEQ;
                C[base0 + l0]            = c0 + b0;
                C[base0 + LSEQ + l0]     = c1 + b1;
                C[base0 + l0 + 8]        = c2 + b0;
                C[base0 + LSEQ + l0 + 8] = c3 + b1;
            } else {
                if (EPI == 3) {
                    *(float2*)&C[(size_t)r0 * ldc + cn]       = make_float2(c0, c1);
                    *(float2*)&C[(size_t)(r0 + 8) * ldc + cn] = make_float2(c2, c3);
                }
                __nv_bfloat162 h0 = __floats2bfloat162_rn(c0, c1);
                __nv_bfloat162 h1 = __floats2bfloat162_rn(c2, c3);
                __nv_bfloat162 l0v = __floats2bfloat162_rn(c0 - __bfloat162float(h0.x),
                                                           c1 - __bfloat162float(h0.y));
                __nv_bfloat162 l1v = __floats2bfloat162_rn(c2 - __bfloat162float(h1.x),
                                                           c3 - __bfloat162float(h1.y));
                *(__nv_bfloat162*)&Ch[(size_t)r0 * ldc + cn]       = h0;
                *(__nv_bfloat162*)&Ch[(size_t)(r0 + 8) * ldc + cn] = h1;
                *(__nv_bfloat162*)&Cl[(size_t)r0 * ldc + cn]       = l0v;
                *(__nv_bfloat162*)&Cl[(size_t)(r0 + 8) * ldc + cn] = l1v;
            }
        }
    }
}

// ---------------- depthwise causal conv + SiLU (rolling window) ----------------
__global__ void conv_silu_k(const float* __restrict__ cw, const float* __restrict__ cb) {
    int e = blockIdx.x * 256 + threadIdx.x;
    int b = blockIdx.z;
    int l0 = blockIdx.y * 128;
    float w0 = cw[e * 4], w1 = cw[e * 4 + 1], w2 = cw[e * 4 + 2], w3 = cw[e * 4 + 3];
    float bias = cb[e];
    size_t base = (size_t)b * LSEQ * 4096 + e;
    float u0 = (l0 >= 3) ? g_xz[base + (size_t)(l0 - 3) * 4096] : 0.f;
    float u1 = (l0 >= 2) ? g_xz[base + (size_t)(l0 - 2) * 4096] : 0.f;
    float u2 = (l0 >= 1) ? g_xz[base + (size_t)(l0 - 1) * 4096] : 0.f;
    for (int l = l0; l < l0 + 128; l++) {
        float u3 = g_xz[base + (size_t)l * 4096];
        float v = fmaf(w0, u0, fmaf(w1, u1, fmaf(w2, u2, fmaf(w3, u3, bias))));
        float s = siluf(v);
        size_t o = (size_t)(b * LSEQ + l) * DINNER + e;
        g_ucf[o] = s;
        __nv_bfloat16 h = __float2bfloat16(s);
        g_ucb[o] = h;
        g_ucb[SZ_UC + o] = __float2bfloat16(s - __bfloat162float(h));
        u0 = u1; u1 = u2; u2 = u3;
    }
}

// ---------------- selective scan ----------------
__global__ void scan_k(const float* __restrict__ A_log, const float* __restrict__ Dv) {
    int g = blockIdx.x * 16 + (threadIdx.x >> 4);
    int n = threadIdx.x & 15;
    int b = g >> 11;
    int d = g & (DINNER - 1);

    float Acoef = -__expf(A_log[d * DSTATE + n]);
    float Dd = Dv[d];
    float h = 0.f;
    size_t rowbase = (size_t)b * LSEQ;

    for (int l = 0; l < LSEQ; l++) {
        size_t r = rowbase + l;
        float dval = g_delta[r * DINNER + d];
        float uval = g_ucf [r * DINNER + d];
        float Bv = g_xdf[r * XPN + DTRANK + n];
        float Cv = g_xdf[r * XPN + DTRANK + DSTATE + n];
        float dA = __expf(dval * Acoef);
        h = fmaf(dA, h, dval * Bv * uval);
        float p = h * Cv;
        p += __shfl_xor_sync(0xffffffffu, p, 1);
        p += __shfl_xor_sync(0xffffffffu, p, 2);
        p += __shfl_xor_sync(0xffffffffu, p, 4);
        p += __shfl_xor_sync(0xffffffffu, p, 8);
        if (n == 0) {
            float z = g_xz[r * 4096 + DINNER + d];
            float yv = (p + uval * Dd) * siluf(z);
            __nv_bfloat16 hh = __float2bfloat16(yv);
            g_yb[r * DINNER + d] = hh;
            g_yb[SZ_Y + r * DINNER + d] = __float2bfloat16(yv - __bfloat162float(hh));
        }
    }
}

// ---------------- launch ----------------
extern "C" void kernel_launch(void* const* d_in, const int* in_sizes, int n_in,
                              void* d_out, int out_size)
{
    const float* x          = (const float*)d_in[0];
    const float* in_proj_w  = (const float*)d_in[1];
    const float* conv_w     = (const float*)d_in[2];
    const float* conv_b     = (const float*)d_in[3];
    const float* x_proj_w   = (const float*)d_in[4];
    const float* dt_proj_w  = (const float*)d_in[5];
    const float* dt_proj_b  = (const float*)d_in[6];
    const float* A_log      = (const float*)d_in[7];
    const float* Dv         = (const float*)d_in[8];
    const float* out_proj_w = (const float*)d_in[9];
    const float* proj_w     = (const float*)d_in[10];
    const float* proj_b     = (const float*)d_in[11];
    float* out = (float*)d_out;

    __nv_bfloat16 *w1b, *wxb, *wdb, *wob, *wpb, *xTb, *ucb, *xdb, *yb, *o1b;
    float *xz, *ucf, *xdf, *delta;
    cudaGetSymbolAddress((void**)&w1b, g_w1b);
    cudaGetSymbolAddress((void**)&wxb, g_wxb);
    cudaGetSymbolAddress((void**)&wdb, g_wdb);
    cudaGetSymbolAddress((void**)&wob, g_wob);
    cudaGetSymbolAddress((void**)&wpb, g_wpb);
    cudaGetSymbolAddress((void**)&xTb, g_xTb);
    cudaGetSymbolAddress((void**)&ucb, g_ucb);
    cudaGetSymbolAddress((void**)&xdb, g_xdb);
    cudaGetSymbolAddress((void**)&yb,  g_yb);
    cudaGetSymbolAddress((void**)&o1b, g_o1b);
    cudaGetSymbolAddress((void**)&xz,    g_xz);
    cudaGetSymbolAddress((void**)&ucf,   g_ucf);
    cudaGetSymbolAddress((void**)&xdf,   g_xdf);
    cudaGetSymbolAddress((void**)&delta, g_delta);

    cudaFuncSetAttribute(hgemm<0>, cudaFuncAttributeMaxDynamicSharedMemorySize, GEMM_SMEM);
    cudaFuncSetAttribute(hgemm<1>, cudaFuncAttributeMaxDynamicSharedMemorySize, GEMM_SMEM);
    cudaFuncSetAttribute(hgemm<2>, cudaFuncAttributeMaxDynamicSharedMemorySize, GEMM_SMEM);
    cudaFuncSetAttribute(hgemm<3>, cudaFuncAttributeMaxDynamicSharedMemorySize, GEMM_SMEM);
    cudaFuncSetAttribute(hgemm<4>, cudaFuncAttributeMaxDynamicSharedMemorySize, GEMM_SMEM);

    // weight conversions + x transpose
    cvt_k<<<(int)(SZ_W1 / 1024), 256>>>(in_proj_w,  w1b, SZ_W1);
    cvt_k<<<(int)(SZ_WX / 1024), 256>>>(x_proj_w,   wxb, SZ_WX);
    cvt_k<<<(int)(SZ_WD / 1024), 256>>>(dt_proj_w,  wdb, SZ_WD);
    cvt_k<<<(int)(SZ_WO / 1024), 256>>>(out_proj_w, wob, SZ_WO);
    cvt_k<<<(int)(SZ_WP / 1024), 256>>>(proj_w,     wpb, SZ_WP);
    transpose_k<<<dim3(LSEQ / 32, DMODEL / 32, BQ), dim3(32, 8)>>>(x);

    // 1) xz = xT @ in_proj_w^T     (8192 x 4096, K=1024)
    hgemm<0><<<dim3(32, 64), 256, GEMM_SMEM>>>(xTb, xTb + SZ_XT, w1b, w1b + SZ_W1,
        nullptr, xz, nullptr, nullptr, BL, 4096, DMODEL, DMODEL, 4096);
    // 2) conv + silu -> ucf + uc hi/lo
    conv_silu_k<<<dim3(DINNER / 256, LSEQ / 128, BQ), 256>>>(conv_w, conv_b);
    // 3) x_dbl = u @ x_proj_w^T    (8192 x 96, K=2048) -> fp32 + hi/lo
    hgemm<3><<<dim3(1, 64), 256, GEMM_SMEM>>>(ucb, ucb + SZ_UC, wxb, wxb + SZ_WX,
        nullptr, xdf, xdb, xdb + SZ_XD, BL, XPN, DINNER, DINNER, XPN);
    // 4) delta = softplus(dt_low @ dt_proj_w^T + b)  (8192 x 2048, K=64)
    hgemm<1><<<dim3(16, 64), 256, GEMM_SMEM>>>(xdb, xdb + SZ_XD, wdb, wdb + SZ_WD,
        dt_proj_b, delta, nullptr, nullptr, BL, DINNER, DTRANK, XPN, DINNER);
    // 5) scan -> y hi/lo
    scan_k<<<512, 256>>>(A_log, Dv);
    // 6) o1 = y @ out_proj_w^T     (8192 x 1024, K=2048) -> hi/lo
    hgemm<4><<<dim3(8, 64), 256, GEMM_SMEM>>>(yb, yb + SZ_Y, wob, wob + SZ_WO,
        nullptr, nullptr, o1b, o1b + SZ_O1, BL, DMODEL, DINNER, DINNER, DMODEL);
    // 7) out = (o1 @ proj_w^T + b), transposed store
    hgemm<2><<<dim3(8, 64), 256, GEMM_SMEM>>>(o1b, o1b + SZ_O1, wpb, wpb + SZ_WP,
        proj_b, out, nullptr, nullptr, BL, DMODEL, DMODEL, DMODEL, 0);
}

// round 9
// speedup vs baseline: 1.3291x; 1.3291x over previous
#include <cuda_runtime.h>
#include <cuda_bf16.h>
#include <cstddef>
#include <cstdint>

// ---------------- problem constants ----------------
#define BQ     4
#define DMODEL 1024
#define LSEQ   2048
#define DINNER 2048
#define DSTATE 16
#define DTRANK 64
#define BL     8192
#define XPN    96

// plane sizes (elements)
#define SZ_W1 ((size_t)4096 * 1024)
#define SZ_WX ((size_t)96 * 2048)
#define SZ_WD ((size_t)2048 * 64)
#define SZ_WO ((size_t)1024 * 2048)
#define SZ_WP ((size_t)1024 * 1024)
#define SZ_XT ((size_t)BL * 1024)
#define SZ_UC ((size_t)BL * 2048)
#define SZ_XD ((size_t)BL * 96)
#define SZ_Y  ((size_t)BL * 2048)
#define SZ_O1 ((size_t)BL * 1024)

// ---------------- scratch: hi plane at [0,N), lo plane at [N,2N) ----------------
__device__ __nv_bfloat16 g_w1b[2 * SZ_W1];
__device__ __nv_bfloat16 g_wxb[2 * SZ_WX];
__device__ __nv_bfloat16 g_wdb[2 * SZ_WD];
__device__ __nv_bfloat16 g_wob[2 * SZ_WO];
__device__ __nv_bfloat16 g_wpb[2 * SZ_WP];
__device__ __nv_bfloat16 g_xTb[2 * SZ_XT];
__device__ __nv_bfloat16 g_ucb[2 * SZ_UC];
__device__ __nv_bfloat16 g_xdb[2 * SZ_XD];
__device__ __nv_bfloat16 g_yb [2 * SZ_Y];
__device__ __nv_bfloat16 g_o1b[2 * SZ_O1];
__device__ float g_xz   [(size_t)BL * 4096];
__device__ float g_ucf  [(size_t)BL * 2048];
__device__ float g_xdf  [(size_t)BL * 96];
__device__ float g_delta[(size_t)BL * 2048];

__device__ __forceinline__ float softplusf(float x) {
    return (x > 20.f) ? x : log1pf(__expf(x));
}
__device__ __forceinline__ float siluf(float x) {
    return x / (1.f + __expf(-x));
}
__device__ __forceinline__ uint32_t smem_u32(const void* p) {
    uint32_t a;
    asm("{ .reg .u64 t; cvta.to.shared.u64 t, %1; cvt.u32.u64 %0, t; }" : "=r"(a) : "l"(p));
    return a;
}

#define MMA_BF16(d, a, b0v, b1v) \
    asm volatile("mma.sync.aligned.m16n8k16.row.col.f32.bf16.bf16.f32 " \
        "{%0,%1,%2,%3}, {%4,%5,%6,%7}, {%8,%9}, {%0,%1,%2,%3};" \
        : "+f"((d)[0]), "+f"((d)[1]), "+f"((d)[2]), "+f"((d)[3]) \
        : "r"((a)[0]), "r"((a)[1]), "r"((a)[2]), "r"((a)[3]), "r"(b0v), "r"(b1v))

#define LDSM4(r, addr) \
    asm volatile("ldmatrix.sync.aligned.m8n8.x4.shared.b16 {%0,%1,%2,%3}, [%4];" \
        : "=r"((r)[0]), "=r"((r)[1]), "=r"((r)[2]), "=r"((r)[3]) : "r"(addr))

#define CP_ASYNC(dst, src) \
    asm volatile("cp.async.cg.shared.global [%0], [%1], 16;" :: "r"(dst), "l"(src) : "memory")
#define CP_ASYNC_Z(dst, src, sz) \
    asm volatile("cp.async.cg.shared.global [%0], [%1], 16, %2;" :: "r"(dst), "l"(src), "r"(sz) : "memory")
#define CP_COMMIT()  asm volatile("cp.async.commit_group;" ::: "memory")
#define CP_WAIT2()   asm volatile("cp.async.wait_group 2;" ::: "memory")

// tile: 128 rows x 64B, XOR swizzle on 16B chunks (verified conflict-free)
__device__ __forceinline__ uint32_t swz(int row, int cc) {
    uint32_t o = (uint32_t)(row * 64 + cc * 16);
    return o ^ ((((uint32_t)row >> 1) & 7u) << 4);
}

#define STAGE_SZ 32768
#define NSTAGE   4
#define GEMM_SMEM (NSTAGE * STAGE_SZ)   // 131072

// ---------------- fp32 -> bf16 hi/lo converter ----------------
__global__ void cvt_k(const float* __restrict__ src, __nv_bfloat16* __restrict__ db, size_t n) {
    size_t i = (size_t)blockIdx.x * 256 + threadIdx.x;
    float4 v = *((const float4*)src + i);
    __nv_bfloat162 h0 = __floats2bfloat162_rn(v.x, v.y);
    __nv_bfloat162 h1 = __floats2bfloat162_rn(v.z, v.w);
    __nv_bfloat162 l0 = __floats2bfloat162_rn(v.x - __bfloat162float(h0.x),
                                              v.y - __bfloat162float(h0.y));
    __nv_bfloat162 l1 = __floats2bfloat162_rn(v.z - __bfloat162float(h1.x),
                                              v.w - __bfloat162float(h1.y));
    ((__nv_bfloat162*)db)[2 * i]     = h0;
    ((__nv_bfloat162*)db)[2 * i + 1] = h1;
    ((__nv_bfloat162*)(db + n))[2 * i]     = l0;
    ((__nv_bfloat162*)(db + n))[2 * i + 1] = l1;
}

// ---------------- x transpose -> hi/lo planes ----------------
__global__ void transpose_k(const float* __restrict__ x) {
    __shared__ float t[32][33];
    int b = blockIdx.z;
    int l0 = blockIdx.x * 32, k0 = blockIdx.y * 32;
    int tx = threadIdx.x, ty = threadIdx.y;
#pragma unroll
    for (int i = 0; i < 4; i++)
        t[ty + 8 * i][tx] = x[((size_t)(b * DMODEL + k0 + ty + 8 * i)) * LSEQ + l0 + tx];
    __syncthreads();
#pragma unroll
    for (int i = 0; i < 4; i++) {
        float v = t[tx][ty + 8 * i];
        size_t o = ((size_t)(b * LSEQ + l0 + ty + 8 * i)) * DMODEL + k0 + tx;
        __nv_bfloat16 h = __float2bfloat16(v);
        g_xTb[o] = h;
        g_xTb[SZ_XT + o] = __float2bfloat16(v - __bfloat162float(h));
    }
}

// ---------------- bf16x3 GEMM: 512 threads, 16 warps (4x4), warp tile 32x32 ----------------
// C[M,N] = A[M,K] @ W[N,K]^T ; A,W given as hi/lo bf16 planes.
// EPI: 0 fp32 | 1 softplus+bias fp32 | 2 transposed+bias fp32 | 3 fp32 + hi/lo | 4 hi/lo only
template<int EPI>
__global__ void __launch_bounds__(512, 1)
hgemm(const __nv_bfloat16* __restrict__ Ah, const __nv_bfloat16* __restrict__ Al,
      const __nv_bfloat16* __restrict__ Bh, const __nv_bfloat16* __restrict__ Bl,
      const float* __restrict__ bias, float* __restrict__ C,
      __nv_bfloat16* __restrict__ Ch, __nv_bfloat16* __restrict__ Cl,
      int M, int N, int K, int lda, int ldc)
{
    extern __shared__ char smem[];
    const uint32_t sb = smem_u32(smem);
    const int tid = threadIdx.x, lane = tid & 31, wid = tid >> 5;
    const int wm = wid >> 2, wn = wid & 3;       // 4 x 4 warp grid
    const int bm = blockIdx.y * 128, bn = blockIdx.x * 128;
    const int nc = K >> 5;

    // ldmatrix lane bases
    const int ar0 = wm * 32 + (lane & 15);
    const uint32_t akh = (uint32_t)(lane >> 4) << 4;
    const uint32_t ab0 = swz(ar0, 0) ^ akh;
    const uint32_t ab1 = swz(ar0 + 16, 0) ^ akh;
    const int brlane = wn * 32 + (lane & 15);
    const uint32_t bb0 = swz(brlane, 0) ^ akh;
    const uint32_t bb1 = swz(brlane + 16, 0) ^ akh;

    float acc[2][4][4];
#pragma unroll
    for (int i = 0; i < 2; i++)
#pragma unroll
        for (int j = 0; j < 4; j++)
#pragma unroll
            for (int t = 0; t < 4; t++) acc[i][j][t] = 0.f;

    auto issue = [&](int chunk, int s) {
        const uint32_t stage = sb + s * STAGE_SZ;
        const int k0 = chunk * 32;
#pragma unroll
        for (int q = 0; q < 4; q++) {
            int c  = q * 512 + tid;               // 2048 16B-chunks per stage
            int tl = c >> 9, r = (c >> 2) & 127, cc = c & 3;
            uint32_t so = stage + tl * 8192 + swz(r, cc);
            if (tl < 2) {
                const __nv_bfloat16* src = (tl == 0 ? Ah : Al)
                    + (size_t)(bm + r) * lda + k0 + cc * 8;
                CP_ASYNC(so, src);
            } else {
                int n = bn + r;
                int ok = (n < N);
                const __nv_bfloat16* src = (tl == 2 ? Bh : Bl)
                    + (size_t)(ok ? n : 0) * K + k0 + cc * 8;
                CP_ASYNC_Z(so, src, ok ? 16 : 0);
            }
        }
    };

    // prologue: 3 commits, real or empty
    issue(0, 0); CP_COMMIT();
    if (nc > 1) issue(1, 1);
    CP_COMMIT();
    if (nc > 2) issue(2, 2);
    CP_COMMIT();

    for (int c = 0; c < nc; c++) {
        CP_WAIT2();
        __syncthreads();
        if (c + 3 < nc) issue(c + 3, (c + 3) & (NSTAGE - 1));
        CP_COMMIT();

        const uint32_t st = sb + (c & (NSTAGE - 1)) * STAGE_SZ;
#pragma unroll
        for (int ks = 0; ks < 2; ks++) {
            const uint32_t kx = (uint32_t)ks << 5;
            uint32_t ah0[4], ah1[4], al0[4], al1[4];
            LDSM4(ah0, st + (ab0 ^ kx));
            LDSM4(ah1, st + (ab1 ^ kx));
            LDSM4(al0, st + 8192 + (ab0 ^ kx));
            LDSM4(al1, st + 8192 + (ab1 ^ kx));
            uint32_t bh0[4], bh1[4], bl0[4], bl1[4];
            LDSM4(bh0, st + 16384 + (bb0 ^ kx));
            LDSM4(bh1, st + 16384 + (bb1 ^ kx));
            LDSM4(bl0, st + 24576 + (bb0 ^ kx));
            LDSM4(bl1, st + 24576 + (bb1 ^ kx));
            // hi*hi
            MMA_BF16(acc[0][0], ah0, bh0[0], bh0[2]);
            MMA_BF16(acc[1][0], ah1, bh0[0], bh0[2]);
            MMA_BF16(acc[0][1], ah0, bh0[1], bh0[3]);
            MMA_BF16(acc[1][1], ah1, bh0[1], bh0[3]);
            MMA_BF16(acc[0][2], ah0, bh1[0], bh1[2]);
            MMA_BF16(acc[1][2], ah1, bh1[0], bh1[2]);
            MMA_BF16(acc[0][3], ah0, bh1[1], bh1[3]);
            MMA_BF16(acc[1][3], ah1, bh1[1], bh1[3]);
            // hi*lo
            MMA_BF16(acc[0][0], ah0, bl0[0], bl0[2]);
            MMA_BF16(acc[1][0], ah1, bl0[0], bl0[2]);
            MMA_BF16(acc[0][1], ah0, bl0[1], bl0[3]);
            MMA_BF16(acc[1][1], ah1, bl0[1], bl0[3]);
            MMA_BF16(acc[0][2], ah0, bl1[0], bl1[2]);
            MMA_BF16(acc[1][2], ah1, bl1[0], bl1[2]);
            MMA_BF16(acc[0][3], ah0, bl1[1], bl1[3]);
            MMA_BF16(acc[1][3], ah1, bl1[1], bl1[3]);
            // lo*hi
            MMA_BF16(acc[0][0], al0, bh0[0], bh0[2]);
            MMA_BF16(acc[1][0], al1, bh0[0], bh0[2]);
            MMA_BF16(acc[0][1], al0, bh0[1], bh0[3]);
            MMA_BF16(acc[1][1], al1, bh0[1], bh0[3]);
            MMA_BF16(acc[0][2], al0, bh1[0], bh1[2]);
            MMA_BF16(acc[1][2], al1, bh1[0], bh1[2]);
            MMA_BF16(acc[0][3], al0, bh1[1], bh1[3]);
            MMA_BF16(acc[1][3], al1, bh1[1], bh1[3]);
        }
        __syncthreads();
    }

    // ---------------- epilogue ----------------
    const int lr = lane >> 2, lc = lane & 3;
#pragma unroll
    for (int i = 0; i < 2; i++) {
#pragma unroll
        for (int j = 0; j < 4; j++) {
            int r0 = bm + wm * 32 + i * 16 + lr;
            int cn = bn + wn * 32 + j * 8 + lc * 2;
            if (cn >= N) continue;
            float c0 = acc[i][j][0], c1 = acc[i][j][1];
            float c2 = acc[i][j][2], c3 = acc[i][j][3];
            if (EPI == 0) {
                *(float2*)&C[(size_t)r0 * ldc + cn]       = make_float2(c0, c1);
                *(float2*)&C[(size_t)(r0 + 8) * ldc + cn] = make_float2(c2, c3);
            } else if (EPI == 1) {
                float b0 = bias[cn], b1 = bias[cn + 1];
                *(float2*)&C[(size_t)r0 * ldc + cn] =
                    make_float2(softplusf(c0 + b0), softplusf(c1 + b1));
                *(float2*)&C[(size_t)(r0 + 8) * ldc + cn] =
                    make_float2(softplusf(c2 + b0), softplusf(c3 + b1));
            } else if (EPI == 2) {
                float b0 = bias[cn], b1 = bias[cn + 1];
                int bb = r0 >> 11, l0 = r0 & (LSEQ - 1);
                size_t base0 = ((size_t)(bb * DMODEL + cn)) * LSEQ;
                C[base0 + l0]            = c0 + b0;
                C[base0 + LSEQ + l0]     = c1 + b1;
                C[base0 + l0 + 8]        = c2 + b0;
                C[base0 + LSEQ + l0 + 8] = c3 + b1;
            } else {
                if (EPI == 3) {
                    *(float2*)&C[(size_t)r0 * ldc + cn]       = make_float2(c0, c1);
                    *(float2*)&C[(size_t)(r0 + 8) * ldc + cn] = make_float2(c2, c3);
                }
                __nv_bfloat162 h0 = __floats2bfloat162_rn(c0, c1);
                __nv_bfloat162 h1 = __floats2bfloat162_rn(c2, c3);
                __nv_bfloat162 l0v = __floats2bfloat162_rn(c0 - __bfloat162float(h0.x),
                                                           c1 - __bfloat162float(h0.y));
                __nv_bfloat162 l1v = __floats2bfloat162_rn(c2 - __bfloat162float(h1.x),
                                                           c3 - __bfloat162float(h1.y));
                *(__nv_bfloat162*)&Ch[(size_t)r0 * ldc + cn]       = h0;
                *(__nv_bfloat162*)&Ch[(size_t)(r0 + 8) * ldc + cn] = h1;
                *(__nv_bfloat162*)&Cl[(size_t)r0 * ldc + cn]       = l0v;
                *(__nv_bfloat162*)&Cl[(size_t)(r0 + 8) * ldc + cn] = l1v;
            }
        }
    }
}

// ---------------- depthwise causal conv + SiLU (rolling window) ----------------
__global__ void conv_silu_k(const float* __restrict__ cw, const float* __restrict__ cb) {
    int e = blockIdx.x * 256 + threadIdx.x;
    int b = blockIdx.z;
    int l0 = blockIdx.y * 128;
    float w0 = cw[e * 4], w1 = cw[e * 4 + 1], w2 = cw[e * 4 + 2], w3 = cw[e * 4 + 3];
    float bias = cb[e];
    size_t base = (size_t)b * LSEQ * 4096 + e;
    float u0 = (l0 >= 3) ? g_xz[base + (size_t)(l0 - 3) * 4096] : 0.f;
    float u1 = (l0 >= 2) ? g_xz[base + (size_t)(l0 - 2) * 4096] : 0.f;
    float u2 = (l0 >= 1) ? g_xz[base + (size_t)(l0 - 1) * 4096] : 0.f;
    for (int l = l0; l < l0 + 128; l++) {
        float u3 = g_xz[base + (size_t)l * 4096];
        float v = fmaf(w0, u0, fmaf(w1, u1, fmaf(w2, u2, fmaf(w3, u3, bias))));
        float s = siluf(v);
        size_t o = (size_t)(b * LSEQ + l) * DINNER + e;
        g_ucf[o] = s;
        __nv_bfloat16 h = __float2bfloat16(s);
        g_ucb[o] = h;
        g_ucb[SZ_UC + o] = __float2bfloat16(s - __bfloat162float(h));
        u0 = u1; u1 = u2; u2 = u3;
    }
}

// ---------------- selective scan ----------------
__global__ void scan_k(const float* __restrict__ A_log, const float* __restrict__ Dv) {
    int g = blockIdx.x * 16 + (threadIdx.x >> 4);
    int n = threadIdx.x & 15;
    int b = g >> 11;
    int d = g & (DINNER - 1);

    float Acoef = -__expf(A_log[d * DSTATE + n]);
    float Dd = Dv[d];
    float h = 0.f;
    size_t rowbase = (size_t)b * LSEQ;

    for (int l = 0; l < LSEQ; l++) {
        size_t r = rowbase + l;
        float dval = g_delta[r * DINNER + d];
        float uval = g_ucf [r * DINNER + d];
        float Bv = g_xdf[r * XPN + DTRANK + n];
        float Cv = g_xdf[r * XPN + DTRANK + DSTATE + n];
        float dA = __expf(dval * Acoef);
        h = fmaf(dA, h, dval * Bv * uval);
        float p = h * Cv;
        p += __shfl_xor_sync(0xffffffffu, p, 1);
        p += __shfl_xor_sync(0xffffffffu, p, 2);
        p += __shfl_xor_sync(0xffffffffu, p, 4);
        p += __shfl_xor_sync(0xffffffffu, p, 8);
        if (n == 0) {
            float z = g_xz[r * 4096 + DINNER + d];
            float yv = (p + uval * Dd) * siluf(z);
            __nv_bfloat16 hh = __float2bfloat16(yv);
            g_yb[r * DINNER + d] = hh;
            g_yb[SZ_Y + r * DINNER + d] = __float2bfloat16(yv - __bfloat162float(hh));
        }
    }
}

// ---------------- launch ----------------
extern "C" void kernel_launch(void* const* d_in, const int* in_sizes, int n_in,
                              void* d_out, int out_size)
{
    const float* x          = (const float*)d_in[0];
    const float* in_proj_w  = (const float*)d_in[1];
    const float* conv_w     = (const float*)d_in[2];
    const float* conv_b     = (const float*)d_in[3];
    const float* x_proj_w   = (const float*)d_in[4];
    const float* dt_proj_w  = (const float*)d_in[5];
    const float* dt_proj_b  = (const float*)d_in[6];
    const float* A_log      = (const float*)d_in[7];
    const float* Dv         = (const float*)d_in[8];
    const float* out_proj_w = (const float*)d_in[9];
    const float* proj_w     = (const float*)d_in[10];
    const float* proj_b     = (const float*)d_in[11];
    float* out = (float*)d_out;

    __nv_bfloat16 *w1b, *wxb, *wdb, *wob, *wpb, *xTb, *ucb, *xdb, *yb, *o1b;
    float *xz, *ucf, *xdf, *delta;
    cudaGetSymbolAddress((void**)&w1b, g_w1b);
    cudaGetSymbolAddress((void**)&wxb, g_wxb);
    cudaGetSymbolAddress((void**)&wdb, g_wdb);
    cudaGetSymbolAddress((void**)&wob, g_wob);
    cudaGetSymbolAddress((void**)&wpb, g_wpb);
    cudaGetSymbolAddress((void**)&xTb, g_xTb);
    cudaGetSymbolAddress((void**)&ucb, g_ucb);
    cudaGetSymbolAddress((void**)&xdb, g_xdb);
    cudaGetSymbolAddress((void**)&yb,  g_yb);
    cudaGetSymbolAddress((void**)&o1b, g_o1b);
    cudaGetSymbolAddress((void**)&xz,    g_xz);
    cudaGetSymbolAddress((void**)&ucf,   g_ucf);
    cudaGetSymbolAddress((void**)&xdf,   g_xdf);
    cudaGetSymbolAddress((void**)&delta, g_delta);

    cudaFuncSetAttribute(hgemm<0>, cudaFuncAttributeMaxDynamicSharedMemorySize, GEMM_SMEM);
    cudaFuncSetAttribute(hgemm<1>, cudaFuncAttributeMaxDynamicSharedMemorySize, GEMM_SMEM);
    cudaFuncSetAttribute(hgemm<2>, cudaFuncAttributeMaxDynamicSharedMemorySize, GEMM_SMEM);
    cudaFuncSetAttribute(hgemm<3>, cudaFuncAttributeMaxDynamicSharedMemorySize, GEMM_SMEM);
    cudaFuncSetAttribute(hgemm<4>, cudaFuncAttributeMaxDynamicSharedMemorySize, GEMM_SMEM);

    // weight conversions + x transpose
    cvt_k<<<(int)(SZ_W1 / 1024), 256>>>(in_proj_w,  w1b, SZ_W1);
    cvt_k<<<(int)(SZ_WX / 1024), 256>>>(x_proj_w,   wxb, SZ_WX);
    cvt_k<<<(int)(SZ_WD / 1024), 256>>>(dt_proj_w,  wdb, SZ_WD);
    cvt_k<<<(int)(SZ_WO / 1024), 256>>>(out_proj_w, wob, SZ_WO);
    cvt_k<<<(int)(SZ_WP / 1024), 256>>>(proj_w,     wpb, SZ_WP);
    transpose_k<<<dim3(LSEQ / 32, DMODEL / 32, BQ), dim3(32, 8)>>>(x);

    // 1) xz = xT @ in_proj_w^T     (8192 x 4096, K=1024)
    hgemm<0><<<dim3(32, 64), 512, GEMM_SMEM>>>(xTb, xTb + SZ_XT, w1b, w1b + SZ_W1,
        nullptr, xz, nullptr, nullptr, BL, 4096, DMODEL, DMODEL, 4096);
    // 2) conv + silu -> ucf + uc hi/lo
    conv_silu_k<<<dim3(DINNER / 256, LSEQ / 128, BQ), 256>>>(conv_w, conv_b);
    // 3) x_dbl = u @ x_proj_w^T    (8192 x 96, K=2048) -> fp32 + hi/lo
    hgemm<3><<<dim3(1, 64), 512, GEMM_SMEM>>>(ucb, ucb + SZ_UC, wxb, wxb + SZ_WX,
        nullptr, xdf, xdb, xdb + SZ_XD, BL, XPN, DINNER, DINNER, XPN);
    // 4) delta = softplus(dt_low @ dt_proj_w^T + b)  (8192 x 2048, K=64)
    hgemm<1><<<dim3(16, 64), 512, GEMM_SMEM>>>(xdb, xdb + SZ_XD, wdb, wdb + SZ_WD,
        dt_proj_b, delta, nullptr, nullptr, BL, DINNER, DTRANK, XPN, DINNER);
    // 5) scan -> y hi/lo
    scan_k<<<512, 256>>>(A_log, Dv);
    // 6) o1 = y @ out_proj_w^T     (8192 x 1024, K=2048) -> hi/lo
    hgemm<4><<<dim3(8, 64), 512, GEMM_SMEM>>>(yb, yb + SZ_Y, wob, wob + SZ_WO,
        nullptr, nullptr, o1b, o1b + SZ_O1, BL, DMODEL, DINNER, DINNER, DMODEL);
    // 7) out = (o1 @ proj_w^T + b), transposed store
    hgemm<2><<<dim3(8, 64), 512, GEMM_SMEM>>>(o1b, o1b + SZ_O1, wpb, wpb + SZ_WP,
        proj_b, out, nullptr, nullptr, BL, DMODEL, DMODEL, DMODEL, 0);
}

// round 11
// speedup vs baseline: 1.7828x; 1.3414x over previous
#include <cuda_runtime.h>
#include <cuda_bf16.h>
#include <cstddef>
#include <cstdint>

// ---------------- problem constants ----------------
#define BQ     4
#define DMODEL 1024
#define LSEQ   2048
#define DINNER 2048
#define DSTATE 16
#define DTRANK 64
#define BL     8192
#define XPN    96

// plane sizes (elements)
#define SZ_W1 ((size_t)4096 * 1024)
#define SZ_WX ((size_t)96 * 2048)
#define SZ_WD ((size_t)2048 * 64)
#define SZ_WO ((size_t)1024 * 2048)
#define SZ_WP ((size_t)1024 * 1024)
#define SZ_XT ((size_t)BL * 1024)
#define SZ_UC ((size_t)BL * 2048)
#define SZ_XD ((size_t)BL * 96)
#define SZ_Y  ((size_t)BL * 2048)
#define SZ_O1 ((size_t)BL * 1024)

// ---------------- scratch: hi plane at [0,N), lo plane at [N,2N) ----------------
__device__ __nv_bfloat16 g_w1b[2 * SZ_W1];
__device__ __nv_bfloat16 g_wxb[2 * SZ_WX];
__device__ __nv_bfloat16 g_wdb[2 * SZ_WD];
__device__ __nv_bfloat16 g_wob[2 * SZ_WO];
__device__ __nv_bfloat16 g_wpb[2 * SZ_WP];
__device__ __nv_bfloat16 g_xTb[2 * SZ_XT];
__device__ __nv_bfloat16 g_ucb[2 * SZ_UC];
__device__ __nv_bfloat16 g_xdb[2 * SZ_XD];
__device__ __nv_bfloat16 g_yb [2 * SZ_Y];
__device__ __nv_bfloat16 g_o1b[2 * SZ_O1];
__device__ float g_xz   [(size_t)BL * 4096];     // u | silu(z)
__device__ float g_ucf  [(size_t)BL * 2048];
__device__ float g_xdf  [(size_t)BL * 96];
__device__ float g_delta[(size_t)BL * 2048];
__device__ float g_part [(size_t)4 * BL * XPN];  // split-K partials for x_proj

__device__ __forceinline__ float softplusf(float x) {
    return (x > 20.f) ? x : log1pf(__expf(x));
}
__device__ __forceinline__ float siluf(float x) {
    return x / (1.f + __expf(-x));
}
__device__ __forceinline__ uint32_t smem_u32(const void* p) {
    uint32_t a;
    asm("{ .reg .u64 t; cvta.to.shared.u64 t, %1; cvt.u32.u64 %0, t; }" : "=r"(a) : "l"(p));
    return a;
}

#define MMA_BF16(d, a, b0v, b1v) \
    asm volatile("mma.sync.aligned.m16n8k16.row.col.f32.bf16.bf16.f32 " \
        "{%0,%1,%2,%3}, {%4,%5,%6,%7}, {%8,%9}, {%0,%1,%2,%3};" \
        : "+f"((d)[0]), "+f"((d)[1]), "+f"((d)[2]), "+f"((d)[3]) \
        : "r"((a)[0]), "r"((a)[1]), "r"((a)[2]), "r"((a)[3]), "r"(b0v), "r"(b1v))

#define LDSM4(r, addr) \
    asm volatile("ldmatrix.sync.aligned.m8n8.x4.shared.b16 {%0,%1,%2,%3}, [%4];" \
        : "=r"((r)[0]), "=r"((r)[1]), "=r"((r)[2]), "=r"((r)[3]) : "r"(addr))

#define CP_ASYNC(dst, src) \
    asm volatile("cp.async.cg.shared.global [%0], [%1], 16;" :: "r"(dst), "l"(src) : "memory")
#define CP_ASYNC_Z(dst, src, sz) \
    asm volatile("cp.async.cg.shared.global [%0], [%1], 16, %2;" :: "r"(dst), "l"(src), "r"(sz) : "memory")
#define CP_COMMIT()  asm volatile("cp.async.commit_group;" ::: "memory")
#define CP_WAIT2()   asm volatile("cp.async.wait_group 2;" ::: "memory")

// tile: 128 rows x 64B, XOR swizzle on 16B chunks (conflict-free)
__device__ __forceinline__ uint32_t swz(int row, int cc) {
    uint32_t o = (uint32_t)(row * 64 + cc * 16);
    return o ^ ((((uint32_t)row >> 1) & 7u) << 4);
}

#define STAGE_SZ 32768
#define NSTAGE   4
#define GEMM_SMEM (NSTAGE * STAGE_SZ)   // 131072

// ---------------- fp32 -> bf16 hi/lo converters ----------------
__device__ __forceinline__ void cvt_body(const float* __restrict__ s,
                                         __nv_bfloat16* __restrict__ d,
                                         size_t n, size_t i) {
    float4 v = *((const float4*)s + i);
    __nv_bfloat162 h0 = __floats2bfloat162_rn(v.x, v.y);
    __nv_bfloat162 h1 = __floats2bfloat162_rn(v.z, v.w);
    __nv_bfloat162 l0 = __floats2bfloat162_rn(v.x - __bfloat162float(h0.x),
                                              v.y - __bfloat162float(h0.y));
    __nv_bfloat162 l1 = __floats2bfloat162_rn(v.z - __bfloat162float(h1.x),
                                              v.w - __bfloat162float(h1.y));
    ((__nv_bfloat162*)d)[2 * i]     = h0;
    ((__nv_bfloat162*)d)[2 * i + 1] = h1;
    ((__nv_bfloat162*)(d + n))[2 * i]     = l0;
    ((__nv_bfloat162*)(d + n))[2 * i + 1] = l1;
}

__global__ void cvt_k(const float* __restrict__ src, __nv_bfloat16* __restrict__ db, size_t n) {
    size_t i = (size_t)blockIdx.x * 256 + threadIdx.x;
    cvt_body(src, db, n, i);
}

__global__ void cvt_rest(const float* s0, __nv_bfloat16* d0, size_t n0,
                         const float* s1, __nv_bfloat16* d1, size_t n1,
                         const float* s2, __nv_bfloat16* d2, size_t n2,
                         const float* s3, __nv_bfloat16* d3, size_t n3) {
    size_t j = (size_t)blockIdx.x * 256 + threadIdx.x;
    if (j < n0 / 4) { cvt_body(s0, d0, n0, j); return; }
    j -= n0 / 4;
    if (j < n1 / 4) { cvt_body(s1, d1, n1, j); return; }
    j -= n1 / 4;
    if (j < n2 / 4) { cvt_body(s2, d2, n2, j); return; }
    j -= n2 / 4;
    if (j < n3 / 4) { cvt_body(s3, d3, n3, j); return; }
}

// ---------------- x transpose -> hi/lo planes ----------------
__global__ void transpose_k(const float* __restrict__ x) {
    __shared__ float t[32][33];
    int b = blockIdx.z;
    int l0 = blockIdx.x * 32, k0 = blockIdx.y * 32;
    int tx = threadIdx.x, ty = threadIdx.y;
#pragma unroll
    for (int i = 0; i < 4; i++)
        t[ty + 8 * i][tx] = x[((size_t)(b * DMODEL + k0 + ty + 8 * i)) * LSEQ + l0 + tx];
    __syncthreads();
#pragma unroll
    for (int i = 0; i < 4; i++) {
        float v = t[tx][ty + 8 * i];
        size_t o = ((size_t)(b * LSEQ + l0 + ty + 8 * i)) * DMODEL + k0 + tx;
        __nv_bfloat16 h = __float2bfloat16(v);
        g_xTb[o] = h;
        g_xTb[SZ_XT + o] = __float2bfloat16(v - __bfloat162float(h));
    }
}

// ---------------- bf16x3 GEMM: 512 threads, 16 warps (4x4), warp tile 32x32 ----------------
// EPI: 0 fp32 (+split-K offset via blockIdx.z) | 1 softplus+bias | 2 transposed+bias
//      4 hi/lo only | 5 fp32, silu applied for cn >= DINNER (in_proj xz)
template<int EPI>
__global__ void __launch_bounds__(512, 1)
hgemm(const __nv_bfloat16* __restrict__ Ah, const __nv_bfloat16* __restrict__ Al,
      const __nv_bfloat16* __restrict__ Bh, const __nv_bfloat16* __restrict__ Bl,
      const float* __restrict__ bias, float* __restrict__ C,
      __nv_bfloat16* __restrict__ Ch, __nv_bfloat16* __restrict__ Cl,
      int M, int N, int K, int lda, int ldc)
{
    extern __shared__ char smem[];
    const uint32_t sb = smem_u32(smem);
    const int tid = threadIdx.x, lane = tid & 31, wid = tid >> 5;
    const int wm = wid >> 2, wn = wid & 3;
    const int bm = blockIdx.y * 128, bn = blockIdx.x * 128;
    const int kw = K / gridDim.z;              // split-K window
    const int kb = blockIdx.z * kw;
    const int nc = kw >> 5;

    const int ar0 = wm * 32 + (lane & 15);
    const uint32_t akh = (uint32_t)(lane >> 4) << 4;
    const uint32_t ab0 = swz(ar0, 0) ^ akh;
    const uint32_t ab1 = swz(ar0 + 16, 0) ^ akh;
    const int brlane = wn * 32 + (lane & 15);
    const uint32_t bb0 = swz(brlane, 0) ^ akh;
    const uint32_t bb1 = swz(brlane + 16, 0) ^ akh;

    float acc[2][4][4];
#pragma unroll
    for (int i = 0; i < 2; i++)
#pragma unroll
        for (int j = 0; j < 4; j++)
#pragma unroll
            for (int t = 0; t < 4; t++) acc[i][j][t] = 0.f;

    auto issue = [&](int chunk, int s) {
        const uint32_t stage = sb + s * STAGE_SZ;
        const int k0 = kb + chunk * 32;
#pragma unroll
        for (int q = 0; q < 4; q++) {
            int c  = q * 512 + tid;
            int tl = c >> 9, r = (c >> 2) & 127, cc = c & 3;
            uint32_t so = stage + tl * 8192 + swz(r, cc);
            if (tl < 2) {
                const __nv_bfloat16* src = (tl == 0 ? Ah : Al)
                    + (size_t)(bm + r) * lda + k0 + cc * 8;
                CP_ASYNC(so, src);
            } else {
                int n = bn + r;
                int ok = (n < N);
                const __nv_bfloat16* src = (tl == 2 ? Bh : Bl)
                    + (size_t)(ok ? n : 0) * K + k0 + cc * 8;
                CP_ASYNC_Z(so, src, ok ? 16 : 0);
            }
        }
    };

    issue(0, 0); CP_COMMIT();
    if (nc > 1) issue(1, 1);
    CP_COMMIT();
    if (nc > 2) issue(2, 2);
    CP_COMMIT();

    for (int c = 0; c < nc; c++) {
        CP_WAIT2();
        __syncthreads();
        if (c + 3 < nc) issue(c + 3, (c + 3) & (NSTAGE - 1));
        CP_COMMIT();

        const uint32_t st = sb + (c & (NSTAGE - 1)) * STAGE_SZ;
#pragma unroll
        for (int ks = 0; ks < 2; ks++) {
            const uint32_t kx = (uint32_t)ks << 5;
            uint32_t ah0[4], ah1[4], al0[4], al1[4];
            LDSM4(ah0, st + (ab0 ^ kx));
            LDSM4(ah1, st + (ab1 ^ kx));
            LDSM4(al0, st + 8192 + (ab0 ^ kx));
            LDSM4(al1, st + 8192 + (ab1 ^ kx));
            uint32_t bh0[4], bh1[4], bl0[4], bl1[4];
            LDSM4(bh0, st + 16384 + (bb0 ^ kx));
            LDSM4(bh1, st + 16384 + (bb1 ^ kx));
            LDSM4(bl0, st + 24576 + (bb0 ^ kx));
            LDSM4(bl1, st + 24576 + (bb1 ^ kx));
            MMA_BF16(acc[0][0], ah0, bh0[0], bh0[2]);
            MMA_BF16(acc[1][0], ah1, bh0[0], bh0[2]);
            MMA_BF16(acc[0][1], ah0, bh0[1], bh0[3]);
            MMA_BF16(acc[1][1], ah1, bh0[1], bh0[3]);
            MMA_BF16(acc[0][2], ah0, bh1[0], bh1[2]);
            MMA_BF16(acc[1][2], ah1, bh1[0], bh1[2]);
            MMA_BF16(acc[0][3], ah0, bh1[1], bh1[3]);
            MMA_BF16(acc[1][3], ah1, bh1[1], bh1[3]);
            MMA_BF16(acc[0][0], ah0, bl0[0], bl0[2]);
            MMA_BF16(acc[1][0], ah1, bl0[0], bl0[2]);
            MMA_BF16(acc[0][1], ah0, bl0[1], bl0[3]);
            MMA_BF16(acc[1][1], ah1, bl0[1], bl0[3]);
            MMA_BF16(acc[0][2], ah0, bl1[0], bl1[2]);
            MMA_BF16(acc[1][2], ah1, bl1[0], bl1[2]);
            MMA_BF16(acc[0][3], ah0, bl1[1], bl1[3]);
            MMA_BF16(acc[1][3], ah1, bl1[1], bl1[3]);
            MMA_BF16(acc[0][0], al0, bh0[0], bh0[2]);
            MMA_BF16(acc[1][0], al1, bh0[0], bh0[2]);
            MMA_BF16(acc[0][1], al0, bh0[1], bh0[3]);
            MMA_BF16(acc[1][1], al1, bh0[1], bh0[3]);
            MMA_BF16(acc[0][2], al0, bh1[0], bh1[2]);
            MMA_BF16(acc[1][2], al1, bh1[0], bh1[2]);
            MMA_BF16(acc[0][3], al0, bh1[1], bh1[3]);
            MMA_BF16(acc[1][3], al1, bh1[1], bh1[3]);
        }
        __syncthreads();
    }

    // ---------------- epilogue ----------------
    const int lr = lane >> 2, lc = lane & 3;
#pragma unroll
    for (int i = 0; i < 2; i++) {
#pragma unroll
        for (int j = 0; j < 4; j++) {
            int r0 = bm + wm * 32 + i * 16 + lr;
            int cn = bn + wn * 32 + j * 8 + lc * 2;
            if (cn >= N) continue;
            float c0 = acc[i][j][0], c1 = acc[i][j][1];
            float c2 = acc[i][j][2], c3 = acc[i][j][3];
            if (EPI == 0) {
                float* Cz = C + (size_t)blockIdx.z * (size_t)M * ldc;
                *(float2*)&Cz[(size_t)r0 * ldc + cn]       = make_float2(c0, c1);
                *(float2*)&Cz[(size_t)(r0 + 8) * ldc + cn] = make_float2(c2, c3);
            } else if (EPI == 5) {
                if (cn >= DINNER) {
                    c0 = siluf(c0); c1 = siluf(c1);
                    c2 = siluf(c2); c3 = siluf(c3);
                }
                *(float2*)&C[(size_t)r0 * ldc + cn]       = make_float2(c0, c1);
                *(float2*)&C[(size_t)(r0 + 8) * ldc + cn] = make_float2(c2, c3);
            } else if (EPI == 1) {
                float b0 = bias[cn], b1 = bias[cn + 1];
                *(float2*)&C[(size_t)r0 * ldc + cn] =
                    make_float2(softplusf(c0 + b0), softplusf(c1 + b1));
                *(float2*)&C[(size_t)(r0 + 8) * ldc + cn] =
                    make_float2(softplusf(c2 + b0), softplusf(c3 + b1));
            } else if (EPI == 2) {
                float b0 = bias[cn], b1 = bias[cn + 1];
                int bb = r0 >> 11, l0 = r0 & (LSEQ - 1);
                size_t base0 = ((size_t)(bb * DMODEL + cn)) * LSEQ;
                C[base0 + l0]            = c0 + b0;
                C[base0 + LSEQ + l0]     = c1 + b1;
                C[base0 + l0 + 8]        = c2 + b0;
                C[base0 + LSEQ + l0 + 8] = c3 + b1;
            } else { // EPI == 4: hi/lo planes only
                __nv_bfloat162 h0 = __floats2bfloat162_rn(c0, c1);
                __nv_bfloat162 h1 = __floats2bfloat162_rn(c2, c3);
                __nv_bfloat162 l0v = __floats2bfloat162_rn(c0 - __bfloat162float(h0.x),
                                                           c1 - __bfloat162float(h0.y));
                __nv_bfloat162 l1v = __floats2bfloat162_rn(c2 - __bfloat162float(h1.x),
                                                           c3 - __bfloat162float(h1.y));
                *(__nv_bfloat162*)&Ch[(size_t)r0 * ldc + cn]       = h0;
                *(__nv_bfloat162*)&Ch[(size_t)(r0 + 8) * ldc + cn] = h1;
                *(__nv_bfloat162*)&Cl[(size_t)r0 * ldc + cn]       = l0v;
                *(__nv_bfloat162*)&Cl[(size_t)(r0 + 8) * ldc + cn] = l1v;
            }
        }
    }
}

// ---------------- split-K reduce for x_proj + hi/lo plane emit ----------------
__global__ void reduce_x() {
    size_t i = (size_t)blockIdx.x * 256 + threadIdx.x;   // < BL*XPN
    const size_t S = (size_t)BL * XPN;
    float s = g_part[i] + g_part[i + S] + g_part[i + 2 * S] + g_part[i + 3 * S];
    g_xdf[i] = s;
    __nv_bfloat16 h = __float2bfloat16(s);
    g_xdb[i] = h;
    g_xdb[SZ_XD + i] = __float2bfloat16(s - __bfloat162float(h));
}

// ---------------- depthwise causal conv + SiLU (rolling window) ----------------
__global__ void conv_silu_k(const float* __restrict__ cw, const float* __restrict__ cb) {
    int e = blockIdx.x * 256 + threadIdx.x;
    int b = blockIdx.z;
    int l0 = blockIdx.y * 128;
    float w0 = cw[e * 4], w1 = cw[e * 4 + 1], w2 = cw[e * 4 + 2], w3 = cw[e * 4 + 3];
    float bias = cb[e];
    size_t base = (size_t)b * LSEQ * 4096 + e;
    float u0 = (l0 >= 3) ? g_xz[base + (size_t)(l0 - 3) * 4096] : 0.f;
    float u1 = (l0 >= 2) ? g_xz[base + (size_t)(l0 - 2) * 4096] : 0.f;
    float u2 = (l0 >= 1) ? g_xz[base + (size_t)(l0 - 1) * 4096] : 0.f;
    for (int l = l0; l < l0 + 128; l++) {
        float u3 = g_xz[base + (size_t)l * 4096];
        float v = fmaf(w0, u0, fmaf(w1, u1, fmaf(w2, u2, fmaf(w3, u3, bias))));
        float s = siluf(v);
        size_t o = (size_t)(b * LSEQ + l) * DINNER + e;
        g_ucf[o] = s;
        __nv_bfloat16 h = __float2bfloat16(s);
        g_ucb[o] = h;
        g_ucb[SZ_UC + o] = __float2bfloat16(s - __bfloat162float(h));
        u0 = u1; u1 = u2; u2 = u3;
    }
}

// ---------------- selective scan: 4 lanes/channel (4 states each), 8 ch/warp ----------------
__global__ void scan_k(const float* __restrict__ A_log, const float* __restrict__ Dv) {
    const int lane = threadIdx.x & 31;
    const int wid  = threadIdx.x >> 5;
    const int g  = blockIdx.x * 64 + wid * 8 + (lane >> 2);   // channel id
    const int nb = (lane & 3) * 4;                             // state base
    const int b = g >> 11, d = g & (DINNER - 1);

    float4 al = *(const float4*)&A_log[d * DSTATE + nb];
    const float Ac0 = -__expf(al.x), Ac1 = -__expf(al.y);
    const float Ac2 = -__expf(al.z), Ac3 = -__expf(al.w);
    const float Dd = Dv[d];
    float h0 = 0.f, h1 = 0.f, h2 = 0.f, h3 = 0.f;
    const size_t rowbase = (size_t)b * LSEQ;

    for (int l = 0; l < LSEQ; l++) {
        size_t r = rowbase + l;
        float dval = g_delta[r * DINNER + d];
        float uval = g_ucf [r * DINNER + d];
        float4 Bv = *(const float4*)&g_xdf[r * XPN + DTRANK + nb];
        float4 Cv = *(const float4*)&g_xdf[r * XPN + DTRANK + DSTATE + nb];
        float dBu = dval * uval;
        h0 = fmaf(__expf(dval * Ac0), h0, dBu * Bv.x);
        h1 = fmaf(__expf(dval * Ac1), h1, dBu * Bv.y);
        h2 = fmaf(__expf(dval * Ac2), h2, dBu * Bv.z);
        h3 = fmaf(__expf(dval * Ac3), h3, dBu * Bv.w);
        float p = fmaf(h0, Cv.x, fmaf(h1, Cv.y, fmaf(h2, Cv.z, h3 * Cv.w)));
        p += __shfl_xor_sync(0xffffffffu, p, 1);
        p += __shfl_xor_sync(0xffffffffu, p, 2);
        if ((lane & 3) == 0) {
            float zs = g_xz[r * 4096 + DINNER + d];   // pre-silu'd in GEMM epilogue
            float yv = (p + uval * Dd) * zs;
            __nv_bfloat16 hh = __float2bfloat16(yv);
            g_yb[r * DINNER + d] = hh;
            g_yb[SZ_Y + r * DINNER + d] = __float2bfloat16(yv - __bfloat162float(hh));
        }
    }
}

// ---------------- launch ----------------
extern "C" void kernel_launch(void* const* d_in, const int* in_sizes, int n_in,
                              void* d_out, int out_size)
{
    const float* x          = (const float*)d_in[0];
    const float* in_proj_w  = (const float*)d_in[1];
    const float* conv_w     = (const float*)d_in[2];
    const float* conv_b     = (const float*)d_in[3];
    const float* x_proj_w   = (const float*)d_in[4];
    const float* dt_proj_w  = (const float*)d_in[5];
    const float* dt_proj_b  = (const float*)d_in[6];
    const float* A_log      = (const float*)d_in[7];
    const float* Dv         = (const float*)d_in[8];
    const float* out_proj_w = (const float*)d_in[9];
    const float* proj_w     = (const float*)d_in[10];
    const float* proj_b     = (const float*)d_in[11];
    float* out = (float*)d_out;

    __nv_bfloat16 *w1b, *wxb, *wdb, *wob, *wpb, *xTb, *ucb, *xdb, *yb, *o1b;
    float *xz, *ucf, *xdf, *delta, *part;
    cudaGetSymbolAddress((void**)&w1b, g_w1b);
    cudaGetSymbolAddress((void**)&wxb, g_wxb);
    cudaGetSymbolAddress((void**)&wdb, g_wdb);
    cudaGetSymbolAddress((void**)&wob, g_wob);
    cudaGetSymbolAddress((void**)&wpb, g_wpb);
    cudaGetSymbolAddress((void**)&xTb, g_xTb);
    cudaGetSymbolAddress((void**)&ucb, g_ucb);
    cudaGetSymbolAddress((void**)&xdb, g_xdb);
    cudaGetSymbolAddress((void**)&yb,  g_yb);
    cudaGetSymbolAddress((void**)&o1b, g_o1b);
    cudaGetSymbolAddress((void**)&xz,    g_xz);
    cudaGetSymbolAddress((void**)&ucf,   g_ucf);
    cudaGetSymbolAddress((void**)&xdf,   g_xdf);
    cudaGetSymbolAddress((void**)&delta, g_delta);
    cudaGetSymbolAddress((void**)&part,  g_part);

    cudaFuncSetAttribute(hgemm<0>, cudaFuncAttributeMaxDynamicSharedMemorySize, GEMM_SMEM);
    cudaFuncSetAttribute(hgemm<1>, cudaFuncAttributeMaxDynamicSharedMemorySize, GEMM_SMEM);
    cudaFuncSetAttribute(hgemm<2>, cudaFuncAttributeMaxDynamicSharedMemorySize, GEMM_SMEM);
    cudaFuncSetAttribute(hgemm<4>, cudaFuncAttributeMaxDynamicSharedMemorySize, GEMM_SMEM);
    cudaFuncSetAttribute(hgemm<5>, cudaFuncAttributeMaxDynamicSharedMemorySize, GEMM_SMEM);

    // [0] in_proj weight conversion
    cvt_k<<<(int)(SZ_W1 / 1024), 256>>>(in_proj_w, w1b, SZ_W1);
    // [1] remaining weight conversions (fused)
    {
        size_t tot4 = (SZ_WX + SZ_WD + SZ_WO + SZ_WP) / 4;
        cvt_rest<<<(int)((tot4 + 255) / 256), 256>>>(
            x_proj_w, wxb, SZ_WX, dt_proj_w, wdb, SZ_WD,
            out_proj_w, wob, SZ_WO, proj_w, wpb, SZ_WP);
    }
    // [2] x transpose
    transpose_k<<<dim3(LSEQ / 32, DMODEL / 32, BQ), dim3(32, 8)>>>(x);
    // [3] in_proj: xz = xT @ W1^T (silu on z half)  <-- profiled slot
    hgemm<5><<<dim3(32, 64), 512, GEMM_SMEM>>>(xTb, xTb + SZ_XT, w1b, w1b + SZ_W1,
        nullptr, xz, nullptr, nullptr, BL, 4096, DMODEL, DMODEL, 4096);
    // [4] conv + silu
    conv_silu_k<<<dim3(DINNER / 256, LSEQ / 128, BQ), 256>>>(conv_w, conv_b);
    // [5] x_proj split-K=4 -> partials
    hgemm<0><<<dim3(1, 64, 4), 512, GEMM_SMEM>>>(ucb, ucb + SZ_UC, wxb, wxb + SZ_WX,
        nullptr, part, nullptr, nullptr, BL, XPN, DINNER, DINNER, XPN);
    // [6] reduce partials -> xdf + planes
    reduce_x<<<(int)((size_t)BL * XPN / 256), 256>>>();
    // [7] delta = softplus(dt_low @ Wd^T + b)
    hgemm<1><<<dim3(16, 64), 512, GEMM_SMEM>>>(xdb, xdb + SZ_XD, wdb, wdb + SZ_WD,
        dt_proj_b, delta, nullptr, nullptr, BL, DINNER, DTRANK, XPN, DINNER);
    // [8] selective scan -> y planes
    scan_k<<<BL / 64, 256>>>(A_log, Dv);
    // [9] o1 = y @ Wo^T -> planes
    hgemm<4><<<dim3(8, 64), 512, GEMM_SMEM>>>(yb, yb + SZ_Y, wob, wob + SZ_WO,
        nullptr, nullptr, o1b, o1b + SZ_O1, BL, DMODEL, DINNER, DINNER, DMODEL);
    // [10] out = (o1 @ Wp^T + b), transposed store
    hgemm<2><<<dim3(8, 64), 512, GEMM_SMEM>>>(o1b, o1b + SZ_O1, wpb, wpb + SZ_WP,
        proj_b, out, nullptr, nullptr, BL, DMODEL, DMODEL, DMODEL, 0);
}

// round 12
// speedup vs baseline: 1.8224x; 1.0222x over previous
#include <cuda_runtime.h>
#include <cuda_bf16.h>
#include <cstddef>
#include <cstdint>

// ---------------- problem constants ----------------
#define BQ     4
#define DMODEL 1024
#define LSEQ   2048
#define DINNER 2048
#define DSTATE 16
#define DTRANK 64
#define BL     8192
#define XPN    96

// plane sizes (elements)
#define SZ_W1 ((size_t)4096 * 1024)
#define SZ_WX ((size_t)96 * 2048)
#define SZ_WD ((size_t)2048 * 64)
#define SZ_WO ((size_t)1024 * 2048)
#define SZ_WP ((size_t)1024 * 1024)
#define SZ_XT ((size_t)BL * 1024)
#define SZ_UC ((size_t)BL * 2048)
#define SZ_XD ((size_t)BL * 96)
#define SZ_Y  ((size_t)BL * 2048)
#define SZ_O1 ((size_t)BL * 1024)

// ---------------- scratch: hi plane at [0,N), lo plane at [N,2N) ----------------
__device__ __nv_bfloat16 g_w1b[2 * SZ_W1];
__device__ __nv_bfloat16 g_wxb[2 * SZ_WX];
__device__ __nv_bfloat16 g_wdb[2 * SZ_WD];
__device__ __nv_bfloat16 g_wob[2 * SZ_WO];
__device__ __nv_bfloat16 g_wpb[2 * SZ_WP];
__device__ __nv_bfloat16 g_xTb[2 * SZ_XT];
__device__ __nv_bfloat16 g_ucb[2 * SZ_UC];
__device__ __nv_bfloat16 g_xdb[2 * SZ_XD];
__device__ __nv_bfloat16 g_yb [2 * SZ_Y];
__device__ __nv_bfloat16 g_o1b[2 * SZ_O1];
__device__ float g_xz   [(size_t)BL * 4096];     // u | silu(z)
__device__ float g_ucf  [(size_t)BL * 2048];
__device__ float g_xdf  [(size_t)BL * 96];
__device__ float g_delta[(size_t)BL * 2048];
__device__ float g_part [(size_t)4 * BL * XPN];  // split-K partials for x_proj

__device__ __forceinline__ float softplusf(float x) {
    return (x > 20.f) ? x : log1pf(__expf(x));
}
__device__ __forceinline__ float siluf(float x) {
    return x / (1.f + __expf(-x));
}
__device__ __forceinline__ uint32_t smem_u32(const void* p) {
    uint32_t a;
    asm("{ .reg .u64 t; cvta.to.shared.u64 t, %1; cvt.u32.u64 %0, t; }" : "=r"(a) : "l"(p));
    return a;
}

#define MMA_BF16(d, a, b0v, b1v) \
    asm volatile("mma.sync.aligned.m16n8k16.row.col.f32.bf16.bf16.f32 " \
        "{%0,%1,%2,%3}, {%4,%5,%6,%7}, {%8,%9}, {%0,%1,%2,%3};" \
        : "+f"((d)[0]), "+f"((d)[1]), "+f"((d)[2]), "+f"((d)[3]) \
        : "r"((a)[0]), "r"((a)[1]), "r"((a)[2]), "r"((a)[3]), "r"(b0v), "r"(b1v))

#define LDSM4(r, addr) \
    asm volatile("ldmatrix.sync.aligned.m8n8.x4.shared.b16 {%0,%1,%2,%3}, [%4];" \
        : "=r"((r)[0]), "=r"((r)[1]), "=r"((r)[2]), "=r"((r)[3]) : "r"(addr))

#define CP_ASYNC(dst, src) \
    asm volatile("cp.async.cg.shared.global [%0], [%1], 16;" :: "r"(dst), "l"(src) : "memory")
#define CP_ASYNC_Z(dst, src, sz) \
    asm volatile("cp.async.cg.shared.global [%0], [%1], 16, %2;" :: "r"(dst), "l"(src), "r"(sz) : "memory")
#define CP_COMMIT()  asm volatile("cp.async.commit_group;" ::: "memory")
#define CP_WAIT2()   asm volatile("cp.async.wait_group 2;" ::: "memory")

// tile: 128 rows x 64B, XOR swizzle on 16B chunks (conflict-free)
__device__ __forceinline__ uint32_t swz(int row, int cc) {
    uint32_t o = (uint32_t)(row * 64 + cc * 16);
    return o ^ ((((uint32_t)row >> 1) & 7u) << 4);
}

#define STAGE_SZ 32768
#define NSTAGE   4
#define GEMM_SMEM (NSTAGE * STAGE_SZ)   // 131072

// ---------------- fp32 -> bf16 hi/lo converters ----------------
__device__ __forceinline__ void cvt_body(const float* __restrict__ s,
                                         __nv_bfloat16* __restrict__ d,
                                         size_t n, size_t i) {
    float4 v = *((const float4*)s + i);
    __nv_bfloat162 h0 = __floats2bfloat162_rn(v.x, v.y);
    __nv_bfloat162 h1 = __floats2bfloat162_rn(v.z, v.w);
    __nv_bfloat162 l0 = __floats2bfloat162_rn(v.x - __bfloat162float(h0.x),
                                              v.y - __bfloat162float(h0.y));
    __nv_bfloat162 l1 = __floats2bfloat162_rn(v.z - __bfloat162float(h1.x),
                                              v.w - __bfloat162float(h1.y));
    ((__nv_bfloat162*)d)[2 * i]     = h0;
    ((__nv_bfloat162*)d)[2 * i + 1] = h1;
    ((__nv_bfloat162*)(d + n))[2 * i]     = l0;
    ((__nv_bfloat162*)(d + n))[2 * i + 1] = l1;
}

__global__ void cvt_k(const float* __restrict__ src, __nv_bfloat16* __restrict__ db, size_t n) {
    size_t i = (size_t)blockIdx.x * 256 + threadIdx.x;
    cvt_body(src, db, n, i);
}

__global__ void cvt_rest(const float* s0, __nv_bfloat16* d0, size_t n0,
                         const float* s1, __nv_bfloat16* d1, size_t n1,
                         const float* s2, __nv_bfloat16* d2, size_t n2,
                         const float* s3, __nv_bfloat16* d3, size_t n3) {
    size_t j = (size_t)blockIdx.x * 256 + threadIdx.x;
    if (j < n0 / 4) { cvt_body(s0, d0, n0, j); return; }
    j -= n0 / 4;
    if (j < n1 / 4) { cvt_body(s1, d1, n1, j); return; }
    j -= n1 / 4;
    if (j < n2 / 4) { cvt_body(s2, d2, n2, j); return; }
    j -= n2 / 4;
    if (j < n3 / 4) { cvt_body(s3, d3, n3, j); return; }
}

// ---------------- x transpose -> hi/lo planes ----------------
__global__ void transpose_k(const float* __restrict__ x) {
    __shared__ float t[32][33];
    int b = blockIdx.z;
    int l0 = blockIdx.x * 32, k0 = blockIdx.y * 32;
    int tx = threadIdx.x, ty = threadIdx.y;
#pragma unroll
    for (int i = 0; i < 4; i++)
        t[ty + 8 * i][tx] = x[((size_t)(b * DMODEL + k0 + ty + 8 * i)) * LSEQ + l0 + tx];
    __syncthreads();
#pragma unroll
    for (int i = 0; i < 4; i++) {
        float v = t[tx][ty + 8 * i];
        size_t o = ((size_t)(b * LSEQ + l0 + ty + 8 * i)) * DMODEL + k0 + tx;
        __nv_bfloat16 h = __float2bfloat16(v);
        g_xTb[o] = h;
        g_xTb[SZ_XT + o] = __float2bfloat16(v - __bfloat162float(h));
    }
}

// ---------------- bf16x3 GEMM: 256 threads, 8 warps (2x4), warp tile 64x32 ----------------
// EPI: 0 fp32 (+split-K offset via blockIdx.z) | 1 softplus+bias | 2 transposed+bias
//      4 hi/lo only | 5 fp32, silu applied for cn >= DINNER (in_proj xz)
template<int EPI>
__global__ void __launch_bounds__(256, 1)
hgemm(const __nv_bfloat16* __restrict__ Ah, const __nv_bfloat16* __restrict__ Al,
      const __nv_bfloat16* __restrict__ Bh, const __nv_bfloat16* __restrict__ Bl,
      const float* __restrict__ bias, float* __restrict__ C,
      __nv_bfloat16* __restrict__ Ch, __nv_bfloat16* __restrict__ Cl,
      int M, int N, int K, int lda, int ldc)
{
    extern __shared__ char smem[];
    const uint32_t sb = smem_u32(smem);
    const int tid = threadIdx.x, lane = tid & 31, wid = tid >> 5;
    const int wm = wid >> 2, wn = wid & 3;       // 2 x 4 warp grid
    const int bm = blockIdx.y * 128, bn = blockIdx.x * 128;
    const int kw = K / gridDim.z;                // split-K window
    const int kb = blockIdx.z * kw;
    const int nc = kw >> 5;

    // ldmatrix lane bases: A rows wm*64 + i*16, B cols wn*32
    const uint32_t akh = (uint32_t)(lane >> 4) << 4;
    uint32_t ab[4];
#pragma unroll
    for (int i = 0; i < 4; i++)
        ab[i] = swz(wm * 64 + i * 16 + (lane & 15), 0) ^ akh;
    const int brl = wn * 32 + (lane & 15);
    const uint32_t bb0 = swz(brl, 0) ^ akh;
    const uint32_t bb1 = swz(brl + 16, 0) ^ akh;

    float acc[4][4][4];
#pragma unroll
    for (int i = 0; i < 4; i++)
#pragma unroll
        for (int j = 0; j < 4; j++)
#pragma unroll
            for (int t = 0; t < 4; t++) acc[i][j][t] = 0.f;

    // ---- persistent loader state (pointers advance 32 elems/chunk) ----
    const int rq = tid >> 2;                     // 0..63
    const int cc = tid & 3;
    const uint32_t s0off = swz(rq, cc);
    const uint32_t s1off = swz(64 + rq, cc);
    const int nB0 = bn + rq, nB1 = bn + 64 + rq;
    const uint32_t okz0 = (nB0 < N) ? 16u : 0u;
    const uint32_t okz1 = (nB1 < N) ? 16u : 0u;
    const __nv_bfloat16* pA0h = Ah + (size_t)(bm + rq) * lda + kb + cc * 8;
    const __nv_bfloat16* pA1h = Ah + (size_t)(bm + 64 + rq) * lda + kb + cc * 8;
    const __nv_bfloat16* pA0l = Al + (size_t)(bm + rq) * lda + kb + cc * 8;
    const __nv_bfloat16* pA1l = Al + (size_t)(bm + 64 + rq) * lda + kb + cc * 8;
    const __nv_bfloat16* pB0h = Bh + (size_t)(nB0 < N ? nB0 : 0) * K + kb + cc * 8;
    const __nv_bfloat16* pB1h = Bh + (size_t)(nB1 < N ? nB1 : 0) * K + kb + cc * 8;
    const __nv_bfloat16* pB0l = Bl + (size_t)(nB0 < N ? nB0 : 0) * K + kb + cc * 8;
    const __nv_bfloat16* pB1l = Bl + (size_t)(nB1 < N ? nB1 : 0) * K + kb + cc * 8;

    auto issue = [&](int s) {
        const uint32_t st = sb + s * STAGE_SZ;
        CP_ASYNC(st + s0off, pA0h);
        CP_ASYNC(st + s1off, pA1h);
        CP_ASYNC(st + 8192 + s0off, pA0l);
        CP_ASYNC(st + 8192 + s1off, pA1l);
        CP_ASYNC_Z(st + 16384 + s0off, pB0h, okz0);
        CP_ASYNC_Z(st + 16384 + s1off, pB1h, okz1);
        CP_ASYNC_Z(st + 24576 + s0off, pB0l, okz0);
        CP_ASYNC_Z(st + 24576 + s1off, pB1l, okz1);
        pA0h += 32; pA1h += 32; pA0l += 32; pA1l += 32;
        pB0h += 32; pB1h += 32; pB0l += 32; pB1l += 32;
    };

    issue(0); CP_COMMIT();
    if (nc > 1) issue(1);
    CP_COMMIT();
    if (nc > 2) issue(2);
    CP_COMMIT();

    for (int c = 0; c < nc; c++) {
        CP_WAIT2();
        __syncthreads();
        if (c + 3 < nc) issue((c + 3) & (NSTAGE - 1));
        CP_COMMIT();

        const uint32_t st = sb + (c & (NSTAGE - 1)) * STAGE_SZ;
#pragma unroll
        for (int ks = 0; ks < 2; ks++) {
            const uint32_t kx = (uint32_t)ks << 5;
            uint32_t ah[4][4], al[4][4], bh[2][4], bl[2][4];
#pragma unroll
            for (int i = 0; i < 4; i++) LDSM4(ah[i], st + (ab[i] ^ kx));
#pragma unroll
            for (int i = 0; i < 4; i++) LDSM4(al[i], st + 8192 + (ab[i] ^ kx));
            LDSM4(bh[0], st + 16384 + (bb0 ^ kx));
            LDSM4(bh[1], st + 16384 + (bb1 ^ kx));
            LDSM4(bl[0], st + 24576 + (bb0 ^ kx));
            LDSM4(bl[1], st + 24576 + (bb1 ^ kx));
            // pass 1: hi*hi
#pragma unroll
            for (int i = 0; i < 4; i++) {
                MMA_BF16(acc[i][0], ah[i], bh[0][0], bh[0][2]);
                MMA_BF16(acc[i][1], ah[i], bh[0][1], bh[0][3]);
                MMA_BF16(acc[i][2], ah[i], bh[1][0], bh[1][2]);
                MMA_BF16(acc[i][3], ah[i], bh[1][1], bh[1][3]);
            }
            // pass 2: hi*lo
#pragma unroll
            for (int i = 0; i < 4; i++) {
                MMA_BF16(acc[i][0], ah[i], bl[0][0], bl[0][2]);
                MMA_BF16(acc[i][1], ah[i], bl[0][1], bl[0][3]);
                MMA_BF16(acc[i][2], ah[i], bl[1][0], bl[1][2]);
                MMA_BF16(acc[i][3], ah[i], bl[1][1], bl[1][3]);
            }
            // pass 3: lo*hi
#pragma unroll
            for (int i = 0; i < 4; i++) {
                MMA_BF16(acc[i][0], al[i], bh[0][0], bh[0][2]);
                MMA_BF16(acc[i][1], al[i], bh[0][1], bh[0][3]);
                MMA_BF16(acc[i][2], al[i], bh[1][0], bh[1][2]);
                MMA_BF16(acc[i][3], al[i], bh[1][1], bh[1][3]);
            }
        }
        __syncthreads();
    }

    // ---------------- epilogue ----------------
    const int lr = lane >> 2, lc = lane & 3;
#pragma unroll
    for (int i = 0; i < 4; i++) {
#pragma unroll
        for (int j = 0; j < 4; j++) {
            int r0 = bm + wm * 64 + i * 16 + lr;
            int cn = bn + wn * 32 + j * 8 + lc * 2;
            if (cn >= N) continue;
            float c0 = acc[i][j][0], c1 = acc[i][j][1];
            float c2 = acc[i][j][2], c3 = acc[i][j][3];
            if (EPI == 0) {
                float* Cz = C + (size_t)blockIdx.z * (size_t)M * ldc;
                *(float2*)&Cz[(size_t)r0 * ldc + cn]       = make_float2(c0, c1);
                *(float2*)&Cz[(size_t)(r0 + 8) * ldc + cn] = make_float2(c2, c3);
            } else if (EPI == 5) {
                if (cn >= DINNER) {
                    c0 = siluf(c0); c1 = siluf(c1);
                    c2 = siluf(c2); c3 = siluf(c3);
                }
                *(float2*)&C[(size_t)r0 * ldc + cn]       = make_float2(c0, c1);
                *(float2*)&C[(size_t)(r0 + 8) * ldc + cn] = make_float2(c2, c3);
            } else if (EPI == 1) {
                float b0 = bias[cn], b1 = bias[cn + 1];
                *(float2*)&C[(size_t)r0 * ldc + cn] =
                    make_float2(softplusf(c0 + b0), softplusf(c1 + b1));
                *(float2*)&C[(size_t)(r0 + 8) * ldc + cn] =
                    make_float2(softplusf(c2 + b0), softplusf(c3 + b1));
            } else if (EPI == 2) {
                float b0 = bias[cn], b1 = bias[cn + 1];
                int bb = r0 >> 11, l0 = r0 & (LSEQ - 1);
                size_t base0 = ((size_t)(bb * DMODEL + cn)) * LSEQ;
                C[base0 + l0]            = c0 + b0;
                C[base0 + LSEQ + l0]     = c1 + b1;
                C[base0 + l0 + 8]        = c2 + b0;
                C[base0 + LSEQ + l0 + 8] = c3 + b1;
            } else { // EPI == 4: hi/lo planes only
                __nv_bfloat162 h0 = __floats2bfloat162_rn(c0, c1);
                __nv_bfloat162 h1 = __floats2bfloat162_rn(c2, c3);
                __nv_bfloat162 l0v = __floats2bfloat162_rn(c0 - __bfloat162float(h0.x),
                                                           c1 - __bfloat162float(h0.y));
                __nv_bfloat162 l1v = __floats2bfloat162_rn(c2 - __bfloat162float(h1.x),
                                                           c3 - __bfloat162float(h1.y));
                *(__nv_bfloat162*)&Ch[(size_t)r0 * ldc + cn]       = h0;
                *(__nv_bfloat162*)&Ch[(size_t)(r0 + 8) * ldc + cn] = h1;
                *(__nv_bfloat162*)&Cl[(size_t)r0 * ldc + cn]       = l0v;
                *(__nv_bfloat162*)&Cl[(size_t)(r0 + 8) * ldc + cn] = l1v;
            }
        }
    }
}

// ---------------- split-K reduce for x_proj + hi/lo plane emit ----------------
__global__ void reduce_x() {
    size_t i = (size_t)blockIdx.x * 256 + threadIdx.x;   // < BL*XPN
    const size_t S = (size_t)BL * XPN;
    float s = g_part[i] + g_part[i + S] + g_part[i + 2 * S] + g_part[i + 3 * S];
    g_xdf[i] = s;
    __nv_bfloat16 h = __float2bfloat16(s);
    g_xdb[i] = h;
    g_xdb[SZ_XD + i] = __float2bfloat16(s - __bfloat162float(h));
}

// ---------------- depthwise causal conv + SiLU (rolling window) ----------------
__global__ void conv_silu_k(const float* __restrict__ cw, const float* __restrict__ cb) {
    int e = blockIdx.x * 256 + threadIdx.x;
    int b = blockIdx.z;
    int l0 = blockIdx.y * 128;
    float w0 = cw[e * 4], w1 = cw[e * 4 + 1], w2 = cw[e * 4 + 2], w3 = cw[e * 4 + 3];
    float bias = cb[e];
    size_t base = (size_t)b * LSEQ * 4096 + e;
    float u0 = (l0 >= 3) ? g_xz[base + (size_t)(l0 - 3) * 4096] : 0.f;
    float u1 = (l0 >= 2) ? g_xz[base + (size_t)(l0 - 2) * 4096] : 0.f;
    float u2 = (l0 >= 1) ? g_xz[base + (size_t)(l0 - 1) * 4096] : 0.f;
    for (int l = l0; l < l0 + 128; l++) {
        float u3 = g_xz[base + (size_t)l * 4096];
        float v = fmaf(w0, u0, fmaf(w1, u1, fmaf(w2, u2, fmaf(w3, u3, bias))));
        float s = siluf(v);
        size_t o = (size_t)(b * LSEQ + l) * DINNER + e;
        g_ucf[o] = s;
        __nv_bfloat16 h = __float2bfloat16(s);
        g_ucb[o] = h;
        g_ucb[SZ_UC + o] = __float2bfloat16(s - __bfloat162float(h));
        u0 = u1; u1 = u2; u2 = u3;
    }
}

// ---------------- selective scan: 4 lanes/channel, prefetch next iteration ----------------
__global__ void scan_k(const float* __restrict__ A_log, const float* __restrict__ Dv) {
    const int lane = threadIdx.x & 31;
    const int wid  = threadIdx.x >> 5;
    const int g  = blockIdx.x * 64 + wid * 8 + (lane >> 2);   // channel id
    const int nb = (lane & 3) * 4;                             // state base
    const int b = g >> 11, d = g & (DINNER - 1);

    float4 al4 = *(const float4*)&A_log[d * DSTATE + nb];
    const float Ac0 = -__expf(al4.x), Ac1 = -__expf(al4.y);
    const float Ac2 = -__expf(al4.z), Ac3 = -__expf(al4.w);
    const float Dd = Dv[d];
    float h0 = 0.f, h1 = 0.f, h2 = 0.f, h3 = 0.f;
    const size_t rowbase = (size_t)b * LSEQ;
    const bool wr = ((lane & 3) == 0);

    // prologue loads for l = 0
    float dval = g_delta[rowbase * DINNER + d];
    float uval = g_ucf [rowbase * DINNER + d];
    float4 Bv = *(const float4*)&g_xdf[rowbase * XPN + DTRANK + nb];
    float4 Cv = *(const float4*)&g_xdf[rowbase * XPN + DTRANK + DSTATE + nb];
    float zs = wr ? g_xz[rowbase * 4096 + DINNER + d] : 0.f;

    for (int l = 0; l < LSEQ; l++) {
        // prefetch l+1 (clamped; harmless re-load on last iter)
        size_t rn = rowbase + ((l + 1 < LSEQ) ? l + 1 : l);
        float dn = g_delta[rn * DINNER + d];
        float un = g_ucf [rn * DINNER + d];
        float4 Bn = *(const float4*)&g_xdf[rn * XPN + DTRANK + nb];
        float4 Cn = *(const float4*)&g_xdf[rn * XPN + DTRANK + DSTATE + nb];
        float zn = wr ? g_xz[rn * 4096 + DINNER + d] : 0.f;

        float dBu = dval * uval;
        h0 = fmaf(__expf(dval * Ac0), h0, dBu * Bv.x);
        h1 = fmaf(__expf(dval * Ac1), h1, dBu * Bv.y);
        h2 = fmaf(__expf(dval * Ac2), h2, dBu * Bv.z);
        h3 = fmaf(__expf(dval * Ac3), h3, dBu * Bv.w);
        float p = fmaf(h0, Cv.x, fmaf(h1, Cv.y, fmaf(h2, Cv.z, h3 * Cv.w)));
        p += __shfl_xor_sync(0xffffffffu, p, 1);
        p += __shfl_xor_sync(0xffffffffu, p, 2);
        if (wr) {
            size_t r = rowbase + l;
            float yv = (p + uval * Dd) * zs;     // zs = silu(z), from in_proj epilogue
            __nv_bfloat16 hh = __float2bfloat16(yv);
            g_yb[r * DINNER + d] = hh;
            g_yb[SZ_Y + r * DINNER + d] = __float2bfloat16(yv - __bfloat162float(hh));
        }
        dval = dn; uval = un; Bv = Bn; Cv = Cn; zs = zn;
    }
}

// ---------------- launch ----------------
extern "C" void kernel_launch(void* const* d_in, const int* in_sizes, int n_in,
                              void* d_out, int out_size)
{
    const float* x          = (const float*)d_in[0];
    const float* in_proj_w  = (const float*)d_in[1];
    const float* conv_w     = (const float*)d_in[2];
    const float* conv_b     = (const float*)d_in[3];
    const float* x_proj_w   = (const float*)d_in[4];
    const float* dt_proj_w  = (const float*)d_in[5];
    const float* dt_proj_b  = (const float*)d_in[6];
    const float* A_log      = (const float*)d_in[7];
    const float* Dv         = (const float*)d_in[8];
    const float* out_proj_w = (const float*)d_in[9];
    const float* proj_w     = (const float*)d_in[10];
    const float* proj_b     = (const float*)d_in[11];
    float* out = (float*)d_out;

    __nv_bfloat16 *w1b, *wxb, *wdb, *wob, *wpb, *xTb, *ucb, *xdb, *yb, *o1b;
    float *xz, *ucf, *xdf, *delta, *part;
    cudaGetSymbolAddress((void**)&w1b, g_w1b);
    cudaGetSymbolAddress((void**)&wxb, g_wxb);
    cudaGetSymbolAddress((void**)&wdb, g_wdb);
    cudaGetSymbolAddress((void**)&wob, g_wob);
    cudaGetSymbolAddress((void**)&wpb, g_wpb);
    cudaGetSymbolAddress((void**)&xTb, g_xTb);
    cudaGetSymbolAddress((void**)&ucb, g_ucb);
    cudaGetSymbolAddress((void**)&xdb, g_xdb);
    cudaGetSymbolAddress((void**)&yb,  g_yb);
    cudaGetSymbolAddress((void**)&o1b, g_o1b);
    cudaGetSymbolAddress((void**)&xz,    g_xz);
    cudaGetSymbolAddress((void**)&ucf,   g_ucf);
    cudaGetSymbolAddress((void**)&xdf,   g_xdf);
    cudaGetSymbolAddress((void**)&delta, g_delta);
    cudaGetSymbolAddress((void**)&part,  g_part);

    cudaFuncSetAttribute(hgemm<0>, cudaFuncAttributeMaxDynamicSharedMemorySize, GEMM_SMEM);
    cudaFuncSetAttribute(hgemm<1>, cudaFuncAttributeMaxDynamicSharedMemorySize, GEMM_SMEM);
    cudaFuncSetAttribute(hgemm<2>, cudaFuncAttributeMaxDynamicSharedMemorySize, GEMM_SMEM);
    cudaFuncSetAttribute(hgemm<4>, cudaFuncAttributeMaxDynamicSharedMemorySize, GEMM_SMEM);
    cudaFuncSetAttribute(hgemm<5>, cudaFuncAttributeMaxDynamicSharedMemorySize, GEMM_SMEM);

    // [0] in_proj weight conversion
    cvt_k<<<(int)(SZ_W1 / 1024), 256>>>(in_proj_w, w1b, SZ_W1);
    // [1] remaining weight conversions (fused)
    {
        size_t tot4 = (SZ_WX + SZ_WD + SZ_WO + SZ_WP) / 4;
        cvt_rest<<<(int)((tot4 + 255) / 256), 256>>>(
            x_proj_w, wxb, SZ_WX, dt_proj_w, wdb, SZ_WD,
            out_proj_w, wob, SZ_WO, proj_w, wpb, SZ_WP);
    }
    // [2] x transpose
    transpose_k<<<dim3(LSEQ / 32, DMODEL / 32, BQ), dim3(32, 8)>>>(x);
    // [3] in_proj: xz = xT @ W1^T (silu on z half)  <-- profiled slot
    hgemm<5><<<dim3(32, 64), 256, GEMM_SMEM>>>(xTb, xTb + SZ_XT, w1b, w1b + SZ_W1,
        nullptr, xz, nullptr, nullptr, BL, 4096, DMODEL, DMODEL, 4096);
    // [4] conv + silu
    conv_silu_k<<<dim3(DINNER / 256, LSEQ / 128, BQ), 256>>>(conv_w, conv_b);
    // [5] x_proj split-K=4 -> partials
    hgemm<0><<<dim3(1, 64, 4), 256, GEMM_SMEM>>>(ucb, ucb + SZ_UC, wxb, wxb + SZ_WX,
        nullptr, part, nullptr, nullptr, BL, XPN, DINNER, DINNER, XPN);
    // [6] reduce partials -> xdf + planes
    reduce_x<<<(int)((size_t)BL * XPN / 256), 256>>>();
    // [7] delta = softplus(dt_low @ Wd^T + b)
    hgemm<1><<<dim3(16, 64), 256, GEMM_SMEM>>>(xdb, xdb + SZ_XD, wdb, wdb + SZ_WD,
        dt_proj_b, delta, nullptr, nullptr, BL, DINNER, DTRANK, XPN, DINNER);
    // [8] selective scan -> y planes
    scan_k<<<BL / 64, 256>>>(A_log, Dv);
    // [9] o1 = y @ Wo^T -> planes
    hgemm<4><<<dim3(8, 64), 256, GEMM_SMEM>>>(yb, yb + SZ_Y, wob, wob + SZ_WO,
        nullptr, nullptr, o1b, o1b + SZ_O1, BL, DMODEL, DINNER, DINNER, DMODEL);
    // [10] out = (o1 @ Wp^T + b), transposed store
    hgemm<2><<<dim3(8, 64), 256, GEMM_SMEM>>>(o1b, o1b + SZ_O1, wpb, wpb + SZ_WP,
        proj_b, out, nullptr, nullptr, BL, DMODEL, DMODEL, DMODEL, 0);
}

// round 13
// speedup vs baseline: 1.8811x; 1.0322x over previous
#include <cuda_runtime.h>
#include <cuda_bf16.h>
#include <cstddef>
#include <cstdint>

// ---------------- problem constants ----------------
#define BQ     4
#define DMODEL 1024
#define LSEQ   2048
#define DINNER 2048
#define DSTATE 16
#define DTRANK 64
#define BL     8192
#define XPN    96

// plane sizes (elements)
#define SZ_W1 ((size_t)4096 * 1024)
#define SZ_WX ((size_t)96 * 2048)
#define SZ_WD ((size_t)2048 * 64)
#define SZ_WO ((size_t)1024 * 2048)
#define SZ_WP ((size_t)1024 * 1024)
#define SZ_XT ((size_t)BL * 1024)
#define SZ_UC ((size_t)BL * 2048)
#define SZ_XD ((size_t)BL * 96)
#define SZ_Y  ((size_t)BL * 2048)
#define SZ_O1 ((size_t)BL * 1024)

// ---------------- scratch: hi plane at [0,N), lo plane at [N,2N) ----------------
__device__ __nv_bfloat16 g_w1b[2 * SZ_W1];
__device__ __nv_bfloat16 g_wxb[2 * SZ_WX];
__device__ __nv_bfloat16 g_wdb[2 * SZ_WD];
__device__ __nv_bfloat16 g_wob[2 * SZ_WO];
__device__ __nv_bfloat16 g_wpb[2 * SZ_WP];
__device__ __nv_bfloat16 g_xTb[2 * SZ_XT];
__device__ __nv_bfloat16 g_ucb[2 * SZ_UC];
__device__ __nv_bfloat16 g_xdb[2 * SZ_XD];
__device__ __nv_bfloat16 g_yb [2 * SZ_Y];
__device__ __nv_bfloat16 g_o1b[2 * SZ_O1];
__device__ float g_xz   [(size_t)BL * 4096];     // u | silu(z)
__device__ float g_ucf  [(size_t)BL * 2048];
__device__ float g_xdf  [(size_t)BL * 96];
__device__ float g_delta[(size_t)BL * 2048];
__device__ float g_part [(size_t)4 * BL * XPN];  // split-K partials for x_proj

__device__ __forceinline__ float softplusf(float x) {
    return (x > 20.f) ? x : log1pf(__expf(x));
}
__device__ __forceinline__ float siluf(float x) {
    return x / (1.f + __expf(-x));
}
__device__ __forceinline__ uint32_t smem_u32(const void* p) {
    uint32_t a;
    asm("{ .reg .u64 t; cvta.to.shared.u64 t, %1; cvt.u32.u64 %0, t; }" : "=r"(a) : "l"(p));
    return a;
}

#define MMA_BF16(d, a, b0v, b1v) \
    asm volatile("mma.sync.aligned.m16n8k16.row.col.f32.bf16.bf16.f32 " \
        "{%0,%1,%2,%3}, {%4,%5,%6,%7}, {%8,%9}, {%0,%1,%2,%3};" \
        : "+f"((d)[0]), "+f"((d)[1]), "+f"((d)[2]), "+f"((d)[3]) \
        : "r"((a)[0]), "r"((a)[1]), "r"((a)[2]), "r"((a)[3]), "r"(b0v), "r"(b1v))

#define LDSM4(r, addr) \
    asm volatile("ldmatrix.sync.aligned.m8n8.x4.shared.b16 {%0,%1,%2,%3}, [%4];" \
        : "=r"((r)[0]), "=r"((r)[1]), "=r"((r)[2]), "=r"((r)[3]) : "r"(addr))

#define CP_ASYNC(dst, src) \
    asm volatile("cp.async.cg.shared.global [%0], [%1], 16;" :: "r"(dst), "l"(src) : "memory")
#define CP_ASYNC_Z(dst, src, sz) \
    asm volatile("cp.async.cg.shared.global [%0], [%1], 16, %2;" :: "r"(dst), "l"(src), "r"(sz) : "memory")
#define CP_COMMIT()  asm volatile("cp.async.commit_group;" ::: "memory")
#define CP_WAIT2()   asm volatile("cp.async.wait_group 2;" ::: "memory")

// tile row: 64B, XOR swizzle on 16B chunks (conflict-free)
__device__ __forceinline__ uint32_t swz(int row, int cc) {
    uint32_t o = (uint32_t)(row * 64 + cc * 16);
    return o ^ ((((uint32_t)row >> 1) & 7u) << 4);
}

// stage layout: Ah[0,16K) Al[16K,32K) Bh[32K,40K) Bl[40K,48K)
#define STAGE_SZ 49152
#define NSTAGE   4
#define GEMM_SMEM (NSTAGE * STAGE_SZ)   // 196608

// ---------------- fp32 -> bf16 hi/lo converters ----------------
__device__ __forceinline__ void cvt_body(const float* __restrict__ s,
                                         __nv_bfloat16* __restrict__ d,
                                         size_t n, size_t i) {
    float4 v = *((const float4*)s + i);
    __nv_bfloat162 h0 = __floats2bfloat162_rn(v.x, v.y);
    __nv_bfloat162 h1 = __floats2bfloat162_rn(v.z, v.w);
    __nv_bfloat162 l0 = __floats2bfloat162_rn(v.x - __bfloat162float(h0.x),
                                              v.y - __bfloat162float(h0.y));
    __nv_bfloat162 l1 = __floats2bfloat162_rn(v.z - __bfloat162float(h1.x),
                                              v.w - __bfloat162float(h1.y));
    ((__nv_bfloat162*)d)[2 * i]     = h0;
    ((__nv_bfloat162*)d)[2 * i + 1] = h1;
    ((__nv_bfloat162*)(d + n))[2 * i]     = l0;
    ((__nv_bfloat162*)(d + n))[2 * i + 1] = l1;
}

__global__ void cvt_k(const float* __restrict__ src, __nv_bfloat16* __restrict__ db, size_t n) {
    size_t i = (size_t)blockIdx.x * 256 + threadIdx.x;
    cvt_body(src, db, n, i);
}

__global__ void cvt_rest(const float* s0, __nv_bfloat16* d0, size_t n0,
                         const float* s1, __nv_bfloat16* d1, size_t n1,
                         const float* s2, __nv_bfloat16* d2, size_t n2,
                         const float* s3, __nv_bfloat16* d3, size_t n3) {
    size_t j = (size_t)blockIdx.x * 256 + threadIdx.x;
    if (j < n0 / 4) { cvt_body(s0, d0, n0, j); return; }
    j -= n0 / 4;
    if (j < n1 / 4) { cvt_body(s1, d1, n1, j); return; }
    j -= n1 / 4;
    if (j < n2 / 4) { cvt_body(s2, d2, n2, j); return; }
    j -= n2 / 4;
    if (j < n3 / 4) { cvt_body(s3, d3, n3, j); return; }
}

// ---------------- x transpose -> hi/lo planes ----------------
__global__ void transpose_k(const float* __restrict__ x) {
    __shared__ float t[32][33];
    int b = blockIdx.z;
    int l0 = blockIdx.x * 32, k0 = blockIdx.y * 32;
    int tx = threadIdx.x, ty = threadIdx.y;
#pragma unroll
    for (int i = 0; i < 4; i++)
        t[ty + 8 * i][tx] = x[((size_t)(b * DMODEL + k0 + ty + 8 * i)) * LSEQ + l0 + tx];
    __syncthreads();
#pragma unroll
    for (int i = 0; i < 4; i++) {
        float v = t[tx][ty + 8 * i];
        size_t o = ((size_t)(b * LSEQ + l0 + ty + 8 * i)) * DMODEL + k0 + tx;
        __nv_bfloat16 h = __float2bfloat16(v);
        g_xTb[o] = h;
        g_xTb[SZ_XT + o] = __float2bfloat16(v - __bfloat162float(h));
    }
}

// ---------------- bf16x3 GEMM: 512 threads, 16 warps (4x4), block 256x128, warp 64x32 ----------------
// EPI: 0 fp32 (+split-K offset via blockIdx.z) | 1 softplus+bias | 2 transposed+bias
//      4 hi/lo only | 5 fp32, silu applied for cn >= DINNER (in_proj xz)
template<int EPI>
__global__ void __launch_bounds__(512, 1)
hgemm(const __nv_bfloat16* __restrict__ Ah, const __nv_bfloat16* __restrict__ Al,
      const __nv_bfloat16* __restrict__ Bh, const __nv_bfloat16* __restrict__ Bl,
      const float* __restrict__ bias, float* __restrict__ C,
      __nv_bfloat16* __restrict__ Ch, __nv_bfloat16* __restrict__ Cl,
      int M, int N, int K, int lda, int ldc)
{
    extern __shared__ char smem[];
    const uint32_t sb = smem_u32(smem);
    const int tid = threadIdx.x, lane = tid & 31, wid = tid >> 5;
    const int wm = wid >> 2, wn = wid & 3;       // 4 x 4 warp grid (rows x cols)
    const int bm = blockIdx.y * 256, bn = blockIdx.x * 128;
    const int kw = K / gridDim.z;                // split-K window
    const int kb = blockIdx.z * kw;
    const int nc = kw >> 5;

    // ldmatrix lane bases: A rows wm*64 + i*16, B cols wn*32
    const uint32_t akh = (uint32_t)(lane >> 4) << 4;
    uint32_t ab[4];
#pragma unroll
    for (int i = 0; i < 4; i++)
        ab[i] = swz(wm * 64 + i * 16 + (lane & 15), 0) ^ akh;
    const int brl = wn * 32 + (lane & 15);
    const uint32_t bb0 = swz(brl, 0) ^ akh;
    const uint32_t bb1 = swz(brl + 16, 0) ^ akh;

    float acc[4][4][4];
#pragma unroll
    for (int i = 0; i < 4; i++)
#pragma unroll
        for (int j = 0; j < 4; j++)
#pragma unroll
            for (int t = 0; t < 4; t++) acc[i][j][t] = 0.f;

    // ---- persistent loader state: 512 thr, A rows rq & 128+rq (hi+lo), B row rq (hi+lo) ----
    const int rq = tid >> 2;                     // 0..127
    const int cc = tid & 3;
    const uint32_t sA0 = swz(rq, cc);
    const uint32_t sA1 = swz(128 + rq, cc);
    const uint32_t sBo = swz(rq, cc);
    const int nB = bn + rq;
    const uint32_t okz = (nB < N) ? 16u : 0u;
    const __nv_bfloat16* pA0h = Ah + (size_t)(bm + rq) * lda + kb + cc * 8;
    const __nv_bfloat16* pA1h = Ah + (size_t)(bm + 128 + rq) * lda + kb + cc * 8;
    const __nv_bfloat16* pA0l = Al + (size_t)(bm + rq) * lda + kb + cc * 8;
    const __nv_bfloat16* pA1l = Al + (size_t)(bm + 128 + rq) * lda + kb + cc * 8;
    const __nv_bfloat16* pBh  = Bh + (size_t)(nB < N ? nB : 0) * K + kb + cc * 8;
    const __nv_bfloat16* pBl  = Bl + (size_t)(nB < N ? nB : 0) * K + kb + cc * 8;

    auto issue = [&](int s) {
        const uint32_t st = sb + s * STAGE_SZ;
        CP_ASYNC(st + sA0, pA0h);
        CP_ASYNC(st + sA1, pA1h);
        CP_ASYNC(st + 16384 + sA0, pA0l);
        CP_ASYNC(st + 16384 + sA1, pA1l);
        CP_ASYNC_Z(st + 32768 + sBo, pBh, okz);
        CP_ASYNC_Z(st + 40960 + sBo, pBl, okz);
        pA0h += 32; pA1h += 32; pA0l += 32; pA1l += 32;
        pBh  += 32; pBl  += 32;
    };

    issue(0); CP_COMMIT();
    if (nc > 1) issue(1);
    CP_COMMIT();
    if (nc > 2) issue(2);
    CP_COMMIT();

    for (int c = 0; c < nc; c++) {
        CP_WAIT2();
        __syncthreads();
        if (c + 3 < nc) issue((c + 3) & (NSTAGE - 1));
        CP_COMMIT();

        const uint32_t st = sb + (c & (NSTAGE - 1)) * STAGE_SZ;
#pragma unroll
        for (int ks = 0; ks < 2; ks++) {
            const uint32_t kx = (uint32_t)ks << 5;
            // stage 1: A-hi + B-hi, pass hi*hi
            uint32_t ah[4][4], bh[2][4];
#pragma unroll
            for (int i = 0; i < 4; i++) LDSM4(ah[i], st + (ab[i] ^ kx));
            LDSM4(bh[0], st + 32768 + (bb0 ^ kx));
            LDSM4(bh[1], st + 32768 + (bb1 ^ kx));
#pragma unroll
            for (int i = 0; i < 4; i++) {
                MMA_BF16(acc[i][0], ah[i], bh[0][0], bh[0][2]);
                MMA_BF16(acc[i][1], ah[i], bh[0][1], bh[0][3]);
                MMA_BF16(acc[i][2], ah[i], bh[1][0], bh[1][2]);
                MMA_BF16(acc[i][3], ah[i], bh[1][1], bh[1][3]);
            }
            // stage 2: B-lo, pass hi*lo
            {
                uint32_t bl[2][4];
                LDSM4(bl[0], st + 40960 + (bb0 ^ kx));
                LDSM4(bl[1], st + 40960 + (bb1 ^ kx));
#pragma unroll
                for (int i = 0; i < 4; i++) {
                    MMA_BF16(acc[i][0], ah[i], bl[0][0], bl[0][2]);
                    MMA_BF16(acc[i][1], ah[i], bl[0][1], bl[0][3]);
                    MMA_BF16(acc[i][2], ah[i], bl[1][0], bl[1][2]);
                    MMA_BF16(acc[i][3], ah[i], bl[1][1], bl[1][3]);
                }
            }
            // stage 3: A-lo (ah dead), pass lo*hi
            {
                uint32_t al[4][4];
#pragma unroll
                for (int i = 0; i < 4; i++) LDSM4(al[i], st + 16384 + (ab[i] ^ kx));
#pragma unroll
                for (int i = 0; i < 4; i++) {
                    MMA_BF16(acc[i][0], al[i], bh[0][0], bh[0][2]);
                    MMA_BF16(acc[i][1], al[i], bh[0][1], bh[0][3]);
                    MMA_BF16(acc[i][2], al[i], bh[1][0], bh[1][2]);
                    MMA_BF16(acc[i][3], al[i], bh[1][1], bh[1][3]);
                }
            }
        }
        __syncthreads();
    }

    // ---------------- epilogue ----------------
    const int lr = lane >> 2, lc = lane & 3;
#pragma unroll
    for (int i = 0; i < 4; i++) {
#pragma unroll
        for (int j = 0; j < 4; j++) {
            int r0 = bm + wm * 64 + i * 16 + lr;
            int cn = bn + wn * 32 + j * 8 + lc * 2;
            if (cn >= N) continue;
            float c0 = acc[i][j][0], c1 = acc[i][j][1];
            float c2 = acc[i][j][2], c3 = acc[i][j][3];
            if (EPI == 0) {
                float* Cz = C + (size_t)blockIdx.z * (size_t)M * ldc;
                *(float2*)&Cz[(size_t)r0 * ldc + cn]       = make_float2(c0, c1);
                *(float2*)&Cz[(size_t)(r0 + 8) * ldc + cn] = make_float2(c2, c3);
            } else if (EPI == 5) {
                if (cn >= DINNER) {
                    c0 = siluf(c0); c1 = siluf(c1);
                    c2 = siluf(c2); c3 = siluf(c3);
                }
                *(float2*)&C[(size_t)r0 * ldc + cn]       = make_float2(c0, c1);
                *(float2*)&C[(size_t)(r0 + 8) * ldc + cn] = make_float2(c2, c3);
            } else if (EPI == 1) {
                float b0 = bias[cn], b1 = bias[cn + 1];
                *(float2*)&C[(size_t)r0 * ldc + cn] =
                    make_float2(softplusf(c0 + b0), softplusf(c1 + b1));
                *(float2*)&C[(size_t)(r0 + 8) * ldc + cn] =
                    make_float2(softplusf(c2 + b0), softplusf(c3 + b1));
            } else if (EPI == 2) {
                float b0 = bias[cn], b1 = bias[cn + 1];
                int bb = r0 >> 11, l0 = r0 & (LSEQ - 1);
                size_t base0 = ((size_t)(bb * DMODEL + cn)) * LSEQ;
                C[base0 + l0]            = c0 + b0;
                C[base0 + LSEQ + l0]     = c1 + b1;
                C[base0 + l0 + 8]        = c2 + b0;
                C[base0 + LSEQ + l0 + 8] = c3 + b1;
            } else { // EPI == 4: hi/lo planes only
                __nv_bfloat162 h0 = __floats2bfloat162_rn(c0, c1);
                __nv_bfloat162 h1 = __floats2bfloat162_rn(c2, c3);
                __nv_bfloat162 l0v = __floats2bfloat162_rn(c0 - __bfloat162float(h0.x),
                                                           c1 - __bfloat162float(h0.y));
                __nv_bfloat162 l1v = __floats2bfloat162_rn(c2 - __bfloat162float(h1.x),
                                                           c3 - __bfloat162float(h1.y));
                *(__nv_bfloat162*)&Ch[(size_t)r0 * ldc + cn]       = h0;
                *(__nv_bfloat162*)&Ch[(size_t)(r0 + 8) * ldc + cn] = h1;
                *(__nv_bfloat162*)&Cl[(size_t)r0 * ldc + cn]       = l0v;
                *(__nv_bfloat162*)&Cl[(size_t)(r0 + 8) * ldc + cn] = l1v;
            }
        }
    }
}

// ---------------- split-K reduce for x_proj + hi/lo plane emit ----------------
__global__ void reduce_x() {
    size_t i = (size_t)blockIdx.x * 256 + threadIdx.x;   // < BL*XPN
    const size_t S = (size_t)BL * XPN;
    float s = g_part[i] + g_part[i + S] + g_part[i + 2 * S] + g_part[i + 3 * S];
    g_xdf[i] = s;
    __nv_bfloat16 h = __float2bfloat16(s);
    g_xdb[i] = h;
    g_xdb[SZ_XD + i] = __float2bfloat16(s - __bfloat162float(h));
}

// ---------------- depthwise causal conv + SiLU (rolling window) ----------------
__global__ void conv_silu_k(const float* __restrict__ cw, const float* __restrict__ cb) {
    int e = blockIdx.x * 256 + threadIdx.x;
    int b = blockIdx.z;
    int l0 = blockIdx.y * 128;
    float w0 = cw[e * 4], w1 = cw[e * 4 + 1], w2 = cw[e * 4 + 2], w3 = cw[e * 4 + 3];
    float bias = cb[e];
    size_t base = (size_t)b * LSEQ * 4096 + e;
    float u0 = (l0 >= 3) ? g_xz[base + (size_t)(l0 - 3) * 4096] : 0.f;
    float u1 = (l0 >= 2) ? g_xz[base + (size_t)(l0 - 2) * 4096] : 0.f;
    float u2 = (l0 >= 1) ? g_xz[base + (size_t)(l0 - 1) * 4096] : 0.f;
    for (int l = l0; l < l0 + 128; l++) {
        float u3 = g_xz[base + (size_t)l * 4096];
        float v = fmaf(w0, u0, fmaf(w1, u1, fmaf(w2, u2, fmaf(w3, u3, bias))));
        float s = siluf(v);
        size_t o = (size_t)(b * LSEQ + l) * DINNER + e;
        g_ucf[o] = s;
        __nv_bfloat16 h = __float2bfloat16(s);
        g_ucb[o] = h;
        g_ucb[SZ_UC + o] = __float2bfloat16(s - __bfloat162float(h));
        u0 = u1; u1 = u2; u2 = u3;
    }
}

// ---------------- selective scan: 4 lanes/channel, prefetch next iteration ----------------
__global__ void scan_k(const float* __restrict__ A_log, const float* __restrict__ Dv) {
    const int lane = threadIdx.x & 31;
    const int wid  = threadIdx.x >> 5;
    const int g  = blockIdx.x * 64 + wid * 8 + (lane >> 2);   // channel id
    const int nb = (lane & 3) * 4;                             // state base
    const int b = g >> 11, d = g & (DINNER - 1);

    float4 al4 = *(const float4*)&A_log[d * DSTATE + nb];
    const float Ac0 = -__expf(al4.x), Ac1 = -__expf(al4.y);
    const float Ac2 = -__expf(al4.z), Ac3 = -__expf(al4.w);
    const float Dd = Dv[d];
    float h0 = 0.f, h1 = 0.f, h2 = 0.f, h3 = 0.f;
    const size_t rowbase = (size_t)b * LSEQ;
    const bool wr = ((lane & 3) == 0);

    float dval = g_delta[rowbase * DINNER + d];
    float uval = g_ucf [rowbase * DINNER + d];
    float4 Bv = *(const float4*)&g_xdf[rowbase * XPN + DTRANK + nb];
    float4 Cv = *(const float4*)&g_xdf[rowbase * XPN + DTRANK + DSTATE + nb];
    float zs = wr ? g_xz[rowbase * 4096 + DINNER + d] : 0.f;

    for (int l = 0; l < LSEQ; l++) {
        size_t rn = rowbase + ((l + 1 < LSEQ) ? l + 1 : l);
        float dn = g_delta[rn * DINNER + d];
        float un = g_ucf [rn * DINNER + d];
        float4 Bn = *(const float4*)&g_xdf[rn * XPN + DTRANK + nb];
        float4 Cn = *(const float4*)&g_xdf[rn * XPN + DTRANK + DSTATE + nb];
        float zn = wr ? g_xz[rn * 4096 + DINNER + d] : 0.f;

        float dBu = dval * uval;
        h0 = fmaf(__expf(dval * Ac0), h0, dBu * Bv.x);
        h1 = fmaf(__expf(dval * Ac1), h1, dBu * Bv.y);
        h2 = fmaf(__expf(dval * Ac2), h2, dBu * Bv.z);
        h3 = fmaf(__expf(dval * Ac3), h3, dBu * Bv.w);
        float p = fmaf(h0, Cv.x, fmaf(h1, Cv.y, fmaf(h2, Cv.z, h3 * Cv.w)));
        p += __shfl_xor_sync(0xffffffffu, p, 1);
        p += __shfl_xor_sync(0xffffffffu, p, 2);
        if (wr) {
            size_t r = rowbase + l;
            float yv = (p + uval * Dd) * zs;
            __nv_bfloat16 hh = __float2bfloat16(yv);
            g_yb[r * DINNER + d] = hh;
            g_yb[SZ_Y + r * DINNER + d] = __float2bfloat16(yv - __bfloat162float(hh));
        }
        dval = dn; uval = un; Bv = Bn; Cv = Cn; zs = zn;
    }
}

// ---------------- launch ----------------
extern "C" void kernel_launch(void* const* d_in, const int* in_sizes, int n_in,
                              void* d_out, int out_size)
{
    const float* x          = (const float*)d_in[0];
    const float* in_proj_w  = (const float*)d_in[1];
    const float* conv_w     = (const float*)d_in[2];
    const float* conv_b     = (const float*)d_in[3];
    const float* x_proj_w   = (const float*)d_in[4];
    const float* dt_proj_w  = (const float*)d_in[5];
    const float* dt_proj_b  = (const float*)d_in[6];
    const float* A_log      = (const float*)d_in[7];
    const float* Dv         = (const float*)d_in[8];
    const float* out_proj_w = (const float*)d_in[9];
    const float* proj_w     = (const float*)d_in[10];
    const float* proj_b     = (const float*)d_in[11];
    float* out = (float*)d_out;

    __nv_bfloat16 *w1b, *wxb, *wdb, *wob, *wpb, *xTb, *ucb, *xdb, *yb, *o1b;
    float *xz, *ucf, *xdf, *delta, *part;
    cudaGetSymbolAddress((void**)&w1b, g_w1b);
    cudaGetSymbolAddress((void**)&wxb, g_wxb);
    cudaGetSymbolAddress((void**)&wdb, g_wdb);
    cudaGetSymbolAddress((void**)&wob, g_wob);
    cudaGetSymbolAddress((void**)&wpb, g_wpb);
    cudaGetSymbolAddress((void**)&xTb, g_xTb);
    cudaGetSymbolAddress((void**)&ucb, g_ucb);
    cudaGetSymbolAddress((void**)&xdb, g_xdb);
    cudaGetSymbolAddress((void**)&yb,  g_yb);
    cudaGetSymbolAddress((void**)&o1b, g_o1b);
    cudaGetSymbolAddress((void**)&xz,    g_xz);
    cudaGetSymbolAddress((void**)&ucf,   g_ucf);
    cudaGetSymbolAddress((void**)&xdf,   g_xdf);
    cudaGetSymbolAddress((void**)&delta, g_delta);
    cudaGetSymbolAddress((void**)&part,  g_part);

    cudaFuncSetAttribute(hgemm<0>, cudaFuncAttributeMaxDynamicSharedMemorySize, GEMM_SMEM);
    cudaFuncSetAttribute(hgemm<1>, cudaFuncAttributeMaxDynamicSharedMemorySize, GEMM_SMEM);
    cudaFuncSetAttribute(hgemm<2>, cudaFuncAttributeMaxDynamicSharedMemorySize, GEMM_SMEM);
    cudaFuncSetAttribute(hgemm<4>, cudaFuncAttributeMaxDynamicSharedMemorySize, GEMM_SMEM);
    cudaFuncSetAttribute(hgemm<5>, cudaFuncAttributeMaxDynamicSharedMemorySize, GEMM_SMEM);

    // [0] in_proj weight conversion
    cvt_k<<<(int)(SZ_W1 / 1024), 256>>>(in_proj_w, w1b, SZ_W1);
    // [1] remaining weight conversions (fused)
    {
        size_t tot4 = (SZ_WX + SZ_WD + SZ_WO + SZ_WP) / 4;
        cvt_rest<<<(int)((tot4 + 255) / 256), 256>>>(
            x_proj_w, wxb, SZ_WX, dt_proj_w, wdb, SZ_WD,
            out_proj_w, wob, SZ_WO, proj_w, wpb, SZ_WP);
    }
    // [2] x transpose
    transpose_k<<<dim3(LSEQ / 32, DMODEL / 32, BQ), dim3(32, 8)>>>(x);
    // [3] in_proj: xz = xT @ W1^T (silu on z half)  <-- profiled slot
    hgemm<5><<<dim3(32, 32), 512, GEMM_SMEM>>>(xTb, xTb + SZ_XT, w1b, w1b + SZ_W1,
        nullptr, xz, nullptr, nullptr, BL, 4096, DMODEL, DMODEL, 4096);
    // [4] conv + silu
    conv_silu_k<<<dim3(DINNER / 256, LSEQ / 128, BQ), 256>>>(conv_w, conv_b);
    // [5] x_proj split-K=4 -> partials
    hgemm<0><<<dim3(1, 32, 4), 512, GEMM_SMEM>>>(ucb, ucb + SZ_UC, wxb, wxb + SZ_WX,
        nullptr, part, nullptr, nullptr, BL, XPN, DINNER, DINNER, XPN);
    // [6] reduce partials -> xdf + planes
    reduce_x<<<(int)((size_t)BL * XPN / 256), 256>>>();
    // [7] delta = softplus(dt_low @ Wd^T + b)
    hgemm<1><<<dim3(16, 32), 512, GEMM_SMEM>>>(xdb, xdb + SZ_XD, wdb, wdb + SZ_WD,
        dt_proj_b, delta, nullptr, nullptr, BL, DINNER, DTRANK, XPN, DINNER);
    // [8] selective scan -> y planes
    scan_k<<<BL / 64, 256>>>(A_log, Dv);
    // [9] o1 = y @ Wo^T -> planes
    hgemm<4><<<dim3(8, 32), 512, GEMM_SMEM>>>(yb, yb + SZ_Y, wob, wob + SZ_WO,
        nullptr, nullptr, o1b, o1b + SZ_O1, BL, DMODEL, DINNER, DINNER, DMODEL);
    // [10] out = (o1 @ Wp^T + b), transposed store
    hgemm<2><<<dim3(8, 32), 512, GEMM_SMEM>>>(o1b, o1b + SZ_O1, wpb, wpb + SZ_WP,
        proj_b, out, nullptr, nullptr, BL, DMODEL, DMODEL, DMODEL, 0);
}

// round 14
// speedup vs baseline: 1.9587x; 1.0412x over previous
#include <cuda_runtime.h>
#include <cuda_bf16.h>
#include <cstddef>
#include <cstdint>

// ---------------- problem constants ----------------
#define BQ     4
#define DMODEL 1024
#define LSEQ   2048
#define DINNER 2048
#define DSTATE 16
#define DTRANK 64
#define BL     8192
#define XPN    96

// plane sizes (elements)
#define SZ_W1 ((size_t)4096 * 1024)
#define SZ_WX ((size_t)96 * 2048)
#define SZ_WD ((size_t)2048 * 64)
#define SZ_WO ((size_t)1024 * 2048)
#define SZ_WP ((size_t)1024 * 1024)
#define SZ_XT ((size_t)BL * 1024)
#define SZ_UC ((size_t)BL * 2048)
#define SZ_XD ((size_t)BL * 96)
#define SZ_Y  ((size_t)BL * 2048)
#define SZ_O1 ((size_t)BL * 1024)

// ---------------- scratch: hi plane at [0,N), lo plane at [N,2N) ----------------
__device__ __nv_bfloat16 g_w1b[2 * SZ_W1];
__device__ __nv_bfloat16 g_wxb[2 * SZ_WX];
__device__ __nv_bfloat16 g_wdb[2 * SZ_WD];
__device__ __nv_bfloat16 g_wob[2 * SZ_WO];
__device__ __nv_bfloat16 g_wpb[2 * SZ_WP];
__device__ __nv_bfloat16 g_xTb[2 * SZ_XT];
__device__ __nv_bfloat16 g_ucb[2 * SZ_UC];
__device__ __nv_bfloat16 g_xdb[2 * SZ_XD];
__device__ __nv_bfloat16 g_yb [2 * SZ_Y];
__device__ __nv_bfloat16 g_o1b[2 * SZ_O1];
__device__ float g_xz   [(size_t)BL * 4096];     // u | silu(z)
__device__ float g_ucf  [(size_t)BL * 2048];
__device__ float g_xdf  [(size_t)BL * 96];
__device__ float g_delta[(size_t)BL * 2048];
__device__ float g_part [(size_t)4 * BL * XPN];  // split-K partials for x_proj

__device__ __forceinline__ float softplusf(float x) {
    return (x > 20.f) ? x : log1pf(__expf(x));
}
__device__ __forceinline__ float siluf(float x) {
    return x / (1.f + __expf(-x));
}
__device__ __forceinline__ uint32_t smem_u32(const void* p) {
    uint32_t a;
    asm("{ .reg .u64 t; cvta.to.shared.u64 t, %1; cvt.u32.u64 %0, t; }" : "=r"(a) : "l"(p));
    return a;
}

#define MMA_BF16(d, a, b0v, b1v) \
    asm volatile("mma.sync.aligned.m16n8k16.row.col.f32.bf16.bf16.f32 " \
        "{%0,%1,%2,%3}, {%4,%5,%6,%7}, {%8,%9}, {%0,%1,%2,%3};" \
        : "+f"((d)[0]), "+f"((d)[1]), "+f"((d)[2]), "+f"((d)[3]) \
        : "r"((a)[0]), "r"((a)[1]), "r"((a)[2]), "r"((a)[3]), "r"(b0v), "r"(b1v))

#define LDSM4(r, addr) \
    asm volatile("ldmatrix.sync.aligned.m8n8.x4.shared.b16 {%0,%1,%2,%3}, [%4];" \
        : "=r"((r)[0]), "=r"((r)[1]), "=r"((r)[2]), "=r"((r)[3]) : "r"(addr))

#define CP_ASYNC(dst, src) \
    asm volatile("cp.async.cg.shared.global [%0], [%1], 16;" :: "r"(dst), "l"(src) : "memory")
#define CP_ASYNC_Z(dst, src, sz) \
    asm volatile("cp.async.cg.shared.global [%0], [%1], 16, %2;" :: "r"(dst), "l"(src), "r"(sz) : "memory")
#define CP_COMMIT()  asm volatile("cp.async.commit_group;" ::: "memory")
#define CP_WAIT2()   asm volatile("cp.async.wait_group 2;" ::: "memory")
#define CP_WAIT1()   asm volatile("cp.async.wait_group 1;" ::: "memory")

// tile row: 64B, XOR swizzle on 16B chunks (conflict-free)
__device__ __forceinline__ uint32_t swz(int row, int cc) {
    uint32_t o = (uint32_t)(row * 64 + cc * 16);
    return o ^ ((((uint32_t)row >> 1) & 7u) << 4);
}

// stage layout: Ah[0,16K) Al[16K,32K) Bh[32K,40K) Bl[40K,48K)
#define STAGE_SZ 49152
#define NSTAGE   4
#define GEMM_SMEM (NSTAGE * STAGE_SZ)   // 196608

// ---------------- fp32 -> bf16 hi/lo converters ----------------
__device__ __forceinline__ void cvt_body(const float* __restrict__ s,
                                         __nv_bfloat16* __restrict__ d,
                                         size_t n, size_t i) {
    float4 v = *((const float4*)s + i);
    __nv_bfloat162 h0 = __floats2bfloat162_rn(v.x, v.y);
    __nv_bfloat162 h1 = __floats2bfloat162_rn(v.z, v.w);
    __nv_bfloat162 l0 = __floats2bfloat162_rn(v.x - __bfloat162float(h0.x),
                                              v.y - __bfloat162float(h0.y));
    __nv_bfloat162 l1 = __floats2bfloat162_rn(v.z - __bfloat162float(h1.x),
                                              v.w - __bfloat162float(h1.y));
    ((__nv_bfloat162*)d)[2 * i]     = h0;
    ((__nv_bfloat162*)d)[2 * i + 1] = h1;
    ((__nv_bfloat162*)(d + n))[2 * i]     = l0;
    ((__nv_bfloat162*)(d + n))[2 * i + 1] = l1;
}

__global__ void cvt_k(const float* __restrict__ src, __nv_bfloat16* __restrict__ db, size_t n) {
    size_t i = (size_t)blockIdx.x * 256 + threadIdx.x;
    cvt_body(src, db, n, i);
}

__global__ void cvt_rest(const float* s0, __nv_bfloat16* d0, size_t n0,
                         const float* s1, __nv_bfloat16* d1, size_t n1,
                         const float* s2, __nv_bfloat16* d2, size_t n2,
                         const float* s3, __nv_bfloat16* d3, size_t n3) {
    size_t j = (size_t)blockIdx.x * 256 + threadIdx.x;
    if (j < n0 / 4) { cvt_body(s0, d0, n0, j); return; }
    j -= n0 / 4;
    if (j < n1 / 4) { cvt_body(s1, d1, n1, j); return; }
    j -= n1 / 4;
    if (j < n2 / 4) { cvt_body(s2, d2, n2, j); return; }
    j -= n2 / 4;
    if (j < n3 / 4) { cvt_body(s3, d3, n3, j); return; }
}

// ---------------- x transpose -> hi/lo planes ----------------
__global__ void transpose_k(const float* __restrict__ x) {
    __shared__ float t[32][33];
    int b = blockIdx.z;
    int l0 = blockIdx.x * 32, k0 = blockIdx.y * 32;
    int tx = threadIdx.x, ty = threadIdx.y;
#pragma unroll
    for (int i = 0; i < 4; i++)
        t[ty + 8 * i][tx] = x[((size_t)(b * DMODEL + k0 + ty + 8 * i)) * LSEQ + l0 + tx];
    __syncthreads();
#pragma unroll
    for (int i = 0; i < 4; i++) {
        float v = t[tx][ty + 8 * i];
        size_t o = ((size_t)(b * LSEQ + l0 + ty + 8 * i)) * DMODEL + k0 + tx;
        __nv_bfloat16 h = __float2bfloat16(v);
        g_xTb[o] = h;
        g_xTb[SZ_XT + o] = __float2bfloat16(v - __bfloat162float(h));
    }
}

// ---------------- bf16x3 GEMM: 512 threads, 16 warps (4x4), block 256x128, warp 64x32 ----------------
// EPI: 0 fp32 (+split-K offset via blockIdx.z) | 1 softplus+bias | 2 transposed+bias
//      4 hi/lo only | 5 fp32, silu applied for cn >= DINNER (in_proj xz)
template<int EPI>
__global__ void __launch_bounds__(512, 1)
hgemm(const __nv_bfloat16* __restrict__ Ah, const __nv_bfloat16* __restrict__ Al,
      const __nv_bfloat16* __restrict__ Bh, const __nv_bfloat16* __restrict__ Bl,
      const float* __restrict__ bias, float* __restrict__ C,
      __nv_bfloat16* __restrict__ Ch, __nv_bfloat16* __restrict__ Cl,
      int M, int N, int K, int lda, int ldc)
{
    extern __shared__ char smem[];
    const uint32_t sb = smem_u32(smem);
    const int tid = threadIdx.x, lane = tid & 31, wid = tid >> 5;
    const int wm = wid >> 2, wn = wid & 3;       // 4 x 4 warp grid (rows x cols)
    const int bm = blockIdx.y * 256, bn = blockIdx.x * 128;
    const int kw = K / gridDim.z;                // split-K window
    const int kb = blockIdx.z * kw;
    const int nc = kw >> 5;

    const uint32_t akh = (uint32_t)(lane >> 4) << 4;
    uint32_t ab[4];
#pragma unroll
    for (int i = 0; i < 4; i++)
        ab[i] = swz(wm * 64 + i * 16 + (lane & 15), 0) ^ akh;
    const int brl = wn * 32 + (lane & 15);
    const uint32_t bb0 = swz(brl, 0) ^ akh;
    const uint32_t bb1 = swz(brl + 16, 0) ^ akh;

    float acc[4][4][4];
#pragma unroll
    for (int i = 0; i < 4; i++)
#pragma unroll
        for (int j = 0; j < 4; j++)
#pragma unroll
            for (int t = 0; t < 4; t++) acc[i][j][t] = 0.f;

    // ---- persistent loader state ----
    const int rq = tid >> 2;                     // 0..127
    const int cc = tid & 3;
    const uint32_t sA0 = swz(rq, cc);
    const uint32_t sA1 = swz(128 + rq, cc);
    const uint32_t sBo = swz(rq, cc);
    const int nB = bn + rq;
    const uint32_t okz = (nB < N) ? 16u : 0u;
    const __nv_bfloat16* pA0h = Ah + (size_t)(bm + rq) * lda + kb + cc * 8;
    const __nv_bfloat16* pA1h = Ah + (size_t)(bm + 128 + rq) * lda + kb + cc * 8;
    const __nv_bfloat16* pA0l = Al + (size_t)(bm + rq) * lda + kb + cc * 8;
    const __nv_bfloat16* pA1l = Al + (size_t)(bm + 128 + rq) * lda + kb + cc * 8;
    const __nv_bfloat16* pBh  = Bh + (size_t)(nB < N ? nB : 0) * K + kb + cc * 8;
    const __nv_bfloat16* pBl  = Bl + (size_t)(nB < N ? nB : 0) * K + kb + cc * 8;

    auto issue = [&](int s) {
        const uint32_t st = sb + s * STAGE_SZ;
        CP_ASYNC(st + sA0, pA0h);
        CP_ASYNC(st + sA1, pA1h);
        CP_ASYNC(st + 16384 + sA0, pA0l);
        CP_ASYNC(st + 16384 + sA1, pA1l);
        CP_ASYNC_Z(st + 32768 + sBo, pBh, okz);
        CP_ASYNC_Z(st + 40960 + sBo, pBl, okz);
        pA0h += 32; pA1h += 32; pA0l += 32; pA1l += 32;
        pBh  += 32; pBl  += 32;
    };

    issue(0); CP_COMMIT();
    if (nc > 1) issue(1);
    CP_COMMIT();
    if (nc > 2) issue(2);
    CP_COMMIT();

    for (int c = 0; c < nc; c++) {
        CP_WAIT2();
        __syncthreads();                         // single barrier per chunk
        if (c + 3 < nc) issue((c + 3) & (NSTAGE - 1));
        CP_COMMIT();

        const uint32_t st = sb + (c & (NSTAGE - 1)) * STAGE_SZ;
#pragma unroll
        for (int ks = 0; ks < 2; ks++) {
            const uint32_t kx = (uint32_t)ks << 5;
            uint32_t ah[4][4], bh[2][4];
#pragma unroll
            for (int i = 0; i < 4; i++) LDSM4(ah[i], st + (ab[i] ^ kx));
            LDSM4(bh[0], st + 32768 + (bb0 ^ kx));
            LDSM4(bh[1], st + 32768 + (bb1 ^ kx));
#pragma unroll
            for (int i = 0; i < 4; i++) {
                MMA_BF16(acc[i][0], ah[i], bh[0][0], bh[0][2]);
                MMA_BF16(acc[i][1], ah[i], bh[0][1], bh[0][3]);
                MMA_BF16(acc[i][2], ah[i], bh[1][0], bh[1][2]);
                MMA_BF16(acc[i][3], ah[i], bh[1][1], bh[1][3]);
            }
            {
                uint32_t bl[2][4];
                LDSM4(bl[0], st + 40960 + (bb0 ^ kx));
                LDSM4(bl[1], st + 40960 + (bb1 ^ kx));
#pragma unroll
                for (int i = 0; i < 4; i++) {
                    MMA_BF16(acc[i][0], ah[i], bl[0][0], bl[0][2]);
                    MMA_BF16(acc[i][1], ah[i], bl[0][1], bl[0][3]);
                    MMA_BF16(acc[i][2], ah[i], bl[1][0], bl[1][2]);
                    MMA_BF16(acc[i][3], ah[i], bl[1][1], bl[1][3]);
                }
            }
            {
                uint32_t al[4][4];
#pragma unroll
                for (int i = 0; i < 4; i++) LDSM4(al[i], st + 16384 + (ab[i] ^ kx));
#pragma unroll
                for (int i = 0; i < 4; i++) {
                    MMA_BF16(acc[i][0], al[i], bh[0][0], bh[0][2]);
                    MMA_BF16(acc[i][1], al[i], bh[0][1], bh[0][3]);
                    MMA_BF16(acc[i][2], al[i], bh[1][0], bh[1][2]);
                    MMA_BF16(acc[i][3], al[i], bh[1][1], bh[1][3]);
                }
            }
        }
    }

    // ---------------- epilogue ----------------
    const int lr = lane >> 2, lc = lane & 3;
#pragma unroll
    for (int i = 0; i < 4; i++) {
#pragma unroll
        for (int j = 0; j < 4; j++) {
            int r0 = bm + wm * 64 + i * 16 + lr;
            int cn = bn + wn * 32 + j * 8 + lc * 2;
            if (cn >= N) continue;
            float c0 = acc[i][j][0], c1 = acc[i][j][1];
            float c2 = acc[i][j][2], c3 = acc[i][j][3];
            if (EPI == 0) {
                float* Cz = C + (size_t)blockIdx.z * (size_t)M * ldc;
                *(float2*)&Cz[(size_t)r0 * ldc + cn]       = make_float2(c0, c1);
                *(float2*)&Cz[(size_t)(r0 + 8) * ldc + cn] = make_float2(c2, c3);
            } else if (EPI == 5) {
                if (cn >= DINNER) {
                    c0 = siluf(c0); c1 = siluf(c1);
                    c2 = siluf(c2); c3 = siluf(c3);
                }
                *(float2*)&C[(size_t)r0 * ldc + cn]       = make_float2(c0, c1);
                *(float2*)&C[(size_t)(r0 + 8) * ldc + cn] = make_float2(c2, c3);
            } else if (EPI == 1) {
                float b0 = bias[cn], b1 = bias[cn + 1];
                *(float2*)&C[(size_t)r0 * ldc + cn] =
                    make_float2(softplusf(c0 + b0), softplusf(c1 + b1));
                *(float2*)&C[(size_t)(r0 + 8) * ldc + cn] =
                    make_float2(softplusf(c2 + b0), softplusf(c3 + b1));
            } else if (EPI == 2) {
                float b0 = bias[cn], b1 = bias[cn + 1];
                int bb = r0 >> 11, l0 = r0 & (LSEQ - 1);
                size_t base0 = ((size_t)(bb * DMODEL + cn)) * LSEQ;
                C[base0 + l0]            = c0 + b0;
                C[base0 + LSEQ + l0]     = c1 + b1;
                C[base0 + l0 + 8]        = c2 + b0;
                C[base0 + LSEQ + l0 + 8] = c3 + b1;
            } else { // EPI == 4: hi/lo planes only
                __nv_bfloat162 h0 = __floats2bfloat162_rn(c0, c1);
                __nv_bfloat162 h1 = __floats2bfloat162_rn(c2, c3);
                __nv_bfloat162 l0v = __floats2bfloat162_rn(c0 - __bfloat162float(h0.x),
                                                           c1 - __bfloat162float(h0.y));
                __nv_bfloat162 l1v = __floats2bfloat162_rn(c2 - __bfloat162float(h1.x),
                                                           c3 - __bfloat162float(h1.y));
                *(__nv_bfloat162*)&Ch[(size_t)r0 * ldc + cn]       = h0;
                *(__nv_bfloat162*)&Ch[(size_t)(r0 + 8) * ldc + cn] = h1;
                *(__nv_bfloat162*)&Cl[(size_t)r0 * ldc + cn]       = l0v;
                *(__nv_bfloat162*)&Cl[(size_t)(r0 + 8) * ldc + cn] = l1v;
            }
        }
    }
}

// ---------------- split-K reduce for x_proj + hi/lo plane emit ----------------
__global__ void reduce_x() {
    size_t i = (size_t)blockIdx.x * 256 + threadIdx.x;   // < BL*XPN
    const size_t S = (size_t)BL * XPN;
    float s = g_part[i] + g_part[i + S] + g_part[i + 2 * S] + g_part[i + 3 * S];
    g_xdf[i] = s;
    __nv_bfloat16 h = __float2bfloat16(s);
    g_xdb[i] = h;
    g_xdb[SZ_XD + i] = __float2bfloat16(s - __bfloat162float(h));
}

// ---------------- depthwise causal conv + SiLU (rolling window) ----------------
__global__ void conv_silu_k(const float* __restrict__ cw, const float* __restrict__ cb) {
    int e = blockIdx.x * 256 + threadIdx.x;
    int b = blockIdx.z;
    int l0 = blockIdx.y * 128;
    float w0 = cw[e * 4], w1 = cw[e * 4 + 1], w2 = cw[e * 4 + 2], w3 = cw[e * 4 + 3];
    float bias = cb[e];
    size_t base = (size_t)b * LSEQ * 4096 + e;
    float u0 = (l0 >= 3) ? g_xz[base + (size_t)(l0 - 3) * 4096] : 0.f;
    float u1 = (l0 >= 2) ? g_xz[base + (size_t)(l0 - 2) * 4096] : 0.f;
    float u2 = (l0 >= 1) ? g_xz[base + (size_t)(l0 - 1) * 4096] : 0.f;
    for (int l = l0; l < l0 + 128; l++) {
        float u3 = g_xz[base + (size_t)l * 4096];
        float v = fmaf(w0, u0, fmaf(w1, u1, fmaf(w2, u2, fmaf(w3, u3, bias))));
        float s = siluf(v);
        size_t o = (size_t)(b * LSEQ + l) * DINNER + e;
        g_ucf[o] = s;
        __nv_bfloat16 h = __float2bfloat16(s);
        g_ucb[o] = h;
        g_ucb[SZ_UC + o] = __float2bfloat16(s - __bfloat162float(h));
        u0 = u1; u1 = u2; u2 = u3;
    }
}

// ---------------- selective scan: SMEM-staged tiles, 64 ch/block, T=64 ----------------
// stage floats: D[0,4096) U[4096,8192) Z[8192,12288) BC[12288,14336)
#define SC_T 64
#define SC_STF 14336
#define SCAN_SMEM (2 * SC_STF * 4)   // 114688 bytes

__global__ void __launch_bounds__(256, 1)
scan_k(const float* __restrict__ A_log, const float* __restrict__ Dv) {
    extern __shared__ float ss[];
    const int tid = threadIdx.x, lane = tid & 31, wid = tid >> 5;
    const int chB = blockIdx.x * 64;            // global channel base
    const int ch  = wid * 8 + (lane >> 2);      // channel within block, 0..63
    const int g   = chB + ch;
    const int b   = g >> 11, d = g & (DINNER - 1);
    const int d0  = chB & (DINNER - 1);         // block channel base within d
    const int nb  = (lane & 3) * 4;
    const size_t rowbase = (size_t)b * LSEQ;
    const bool wr = ((lane & 3) == 0);

    float4 al4 = *(const float4*)&A_log[d * DSTATE + nb];
    const float Ac0 = -__expf(al4.x), Ac1 = -__expf(al4.y);
    const float Ac2 = -__expf(al4.z), Ac3 = -__expf(al4.w);
    const float Dd = Dv[d];
    float h0 = 0.f, h1 = 0.f, h2 = 0.f, h3 = 0.f;

    const uint32_t sbase = smem_u32(ss);

    auto stage_load = [&](int tile, int s) {
        const uint32_t st = sbase + (uint32_t)s * (SC_STF * 4);
        const int row0 = tile * SC_T;
#pragma unroll
        for (int i = 0; i < 4; i++) {           // D,U,Z: 64x64 floats each
            int q  = tid + i * 256;
            int t  = q >> 4;
            int c4 = (q & 15) * 4;
            size_t r = rowbase + row0 + t;
            uint32_t so = (uint32_t)(t * 64 + c4) * 4;
            CP_ASYNC(st + so,          g_delta + r * DINNER + d0 + c4);
            CP_ASYNC(st + 16384 + so,  g_ucf   + r * DINNER + d0 + c4);
            CP_ASYNC(st + 32768 + so,  g_xz    + r * 4096 + DINNER + d0 + c4);
        }
#pragma unroll
        for (int i = 0; i < 2; i++) {           // BC: 64x32 floats
            int q  = tid + i * 256;
            int t  = q >> 3;
            int c4 = (q & 7) * 4;
            size_t r = rowbase + row0 + t;
            CP_ASYNC(st + 49152 + (uint32_t)(t * 32 + c4) * 4,
                     g_xdf + r * XPN + DTRANK + c4);
        }
    };

    stage_load(0, 0); CP_COMMIT();
    stage_load(1, 1); CP_COMMIT();

    const int NT = LSEQ / SC_T;                 // 32 tiles
    for (int tile = 0; tile < NT; tile++) {
        CP_WAIT1();
        __syncthreads();
        const float* st = ss + (tile & 1) * SC_STF;
        const size_t rb = rowbase + (size_t)tile * SC_T;
#pragma unroll 4
        for (int t = 0; t < SC_T; t++) {
            float dval = st[t * 64 + ch];
            float uval = st[4096 + t * 64 + ch];
            float4 Bv = *(const float4*)&st[12288 + t * 32 + nb];
            float4 Cv = *(const float4*)&st[12288 + t * 32 + 16 + nb];
            float dBu = dval * uval;
            h0 = fmaf(__expf(dval * Ac0), h0, dBu * Bv.x);
            h1 = fmaf(__expf(dval * Ac1), h1, dBu * Bv.y);
            h2 = fmaf(__expf(dval * Ac2), h2, dBu * Bv.z);
            h3 = fmaf(__expf(dval * Ac3), h3, dBu * Bv.w);
            float p = fmaf(h0, Cv.x, fmaf(h1, Cv.y, fmaf(h2, Cv.z, h3 * Cv.w)));
            p += __shfl_xor_sync(0xffffffffu, p, 1);
            p += __shfl_xor_sync(0xffffffffu, p, 2);
            if (wr) {
                float zs = st[8192 + t * 64 + ch];
                float yv = (p + uval * Dd) * zs;
                size_t r = rb + t;
                __nv_bfloat16 hh = __float2bfloat16(yv);
                g_yb[r * DINNER + d] = hh;
                g_yb[SZ_Y + r * DINNER + d] = __float2bfloat16(yv - __bfloat162float(hh));
            }
        }
        __syncthreads();                        // before overwriting this stage
        if (tile + 2 < NT) stage_load(tile + 2, tile & 1);
        CP_COMMIT();
    }
}

// ---------------- launch ----------------
extern "C" void kernel_launch(void* const* d_in, const int* in_sizes, int n_in,
                              void* d_out, int out_size)
{
    const float* x          = (const float*)d_in[0];
    const float* in_proj_w  = (const float*)d_in[1];
    const float* conv_w     = (const float*)d_in[2];
    const float* conv_b     = (const float*)d_in[3];
    const float* x_proj_w   = (const float*)d_in[4];
    const float* dt_proj_w  = (const float*)d_in[5];
    const float* dt_proj_b  = (const float*)d_in[6];
    const float* A_log      = (const float*)d_in[7];
    const float* Dv         = (const float*)d_in[8];
    const float* out_proj_w = (const float*)d_in[9];
    const float* proj_w     = (const float*)d_in[10];
    const float* proj_b     = (const float*)d_in[11];
    float* out = (float*)d_out;

    __nv_bfloat16 *w1b, *wxb, *wdb, *wob, *wpb, *xTb, *ucb, *xdb, *yb, *o1b;
    float *xz, *ucf, *xdf, *delta, *part;
    cudaGetSymbolAddress((void**)&w1b, g_w1b);
    cudaGetSymbolAddress((void**)&wxb, g_wxb);
    cudaGetSymbolAddress((void**)&wdb, g_wdb);
    cudaGetSymbolAddress((void**)&wob, g_wob);
    cudaGetSymbolAddress((void**)&wpb, g_wpb);
    cudaGetSymbolAddress((void**)&xTb, g_xTb);
    cudaGetSymbolAddress((void**)&ucb, g_ucb);
    cudaGetSymbolAddress((void**)&xdb, g_xdb);
    cudaGetSymbolAddress((void**)&yb,  g_yb);
    cudaGetSymbolAddress((void**)&o1b, g_o1b);
    cudaGetSymbolAddress((void**)&xz,    g_xz);
    cudaGetSymbolAddress((void**)&ucf,   g_ucf);
    cudaGetSymbolAddress((void**)&xdf,   g_xdf);
    cudaGetSymbolAddress((void**)&delta, g_delta);
    cudaGetSymbolAddress((void**)&part,  g_part);

    cudaFuncSetAttribute(hgemm<0>, cudaFuncAttributeMaxDynamicSharedMemorySize, GEMM_SMEM);
    cudaFuncSetAttribute(hgemm<1>, cudaFuncAttributeMaxDynamicSharedMemorySize, GEMM_SMEM);
    cudaFuncSetAttribute(hgemm<2>, cudaFuncAttributeMaxDynamicSharedMemorySize, GEMM_SMEM);
    cudaFuncSetAttribute(hgemm<4>, cudaFuncAttributeMaxDynamicSharedMemorySize, GEMM_SMEM);
    cudaFuncSetAttribute(hgemm<5>, cudaFuncAttributeMaxDynamicSharedMemorySize, GEMM_SMEM);
    cudaFuncSetAttribute(scan_k,   cudaFuncAttributeMaxDynamicSharedMemorySize, SCAN_SMEM);

    // [0] in_proj weight conversion
    cvt_k<<<(int)(SZ_W1 / 1024), 256>>>(in_proj_w, w1b, SZ_W1);
    // [1] remaining weight conversions (fused)
    {
        size_t tot4 = (SZ_WX + SZ_WD + SZ_WO + SZ_WP) / 4;
        cvt_rest<<<(int)((tot4 + 255) / 256), 256>>>(
            x_proj_w, wxb, SZ_WX, dt_proj_w, wdb, SZ_WD,
            out_proj_w, wob, SZ_WO, proj_w, wpb, SZ_WP);
    }
    // [2] x transpose
    transpose_k<<<dim3(LSEQ / 32, DMODEL / 32, BQ), dim3(32, 8)>>>(x);
    // [3] in_proj: xz = xT @ W1^T (silu on z half)  <-- profiled slot
    hgemm<5><<<dim3(32, 32), 512, GEMM_SMEM>>>(xTb, xTb + SZ_XT, w1b, w1b + SZ_W1,
        nullptr, xz, nullptr, nullptr, BL, 4096, DMODEL, DMODEL, 4096);
    // [4] conv + silu
    conv_silu_k<<<dim3(DINNER / 256, LSEQ / 128, BQ), 256>>>(conv_w, conv_b);
    // [5] x_proj split-K=4 -> partials
    hgemm<0><<<dim3(1, 32, 4), 512, GEMM_SMEM>>>(ucb, ucb + SZ_UC, wxb, wxb + SZ_WX,
        nullptr, part, nullptr, nullptr, BL, XPN, DINNER, DINNER, XPN);
    // [6] reduce partials -> xdf + planes
    reduce_x<<<(int)((size_t)BL * XPN / 256), 256>>>();
    // [7] delta = softplus(dt_low @ Wd^T + b)
    hgemm<1><<<dim3(16, 32), 512, GEMM_SMEM>>>(xdb, xdb + SZ_XD, wdb, wdb + SZ_WD,
        dt_proj_b, delta, nullptr, nullptr, BL, DINNER, DTRANK, XPN, DINNER);
    // [8] selective scan -> y planes (SMEM-staged)
    scan_k<<<BL / 64, 256, SCAN_SMEM>>>(A_log, Dv);
    // [9] o1 = y @ Wo^T -> planes
    hgemm<4><<<dim3(8, 32), 512, GEMM_SMEM>>>(yb, yb + SZ_Y, wob, wob + SZ_WO,
        nullptr, nullptr, o1b, o1b + SZ_O1, BL, DMODEL, DINNER, DINNER, DMODEL);
    // [10] out = (o1 @ Wp^T + b), transposed store
    hgemm<2><<<dim3(8, 32), 512, GEMM_SMEM>>>(o1b, o1b + SZ_O1, wpb, wpb + SZ_WP,
        proj_b, out, nullptr, nullptr, BL, DMODEL, DMODEL, DMODEL, 0);
}

// round 15
// speedup vs baseline: 3.1586x; 1.6126x over previous
#include <cuda_runtime.h>
#include <cuda_bf16.h>
#include <cstddef>
#include <cstdint>

// ---------------- problem constants ----------------
#define BQ     4
#define DMODEL 1024
#define LSEQ   2048
#define DINNER 2048
#define DSTATE 16
#define DTRANK 64
#define BL     8192
#define XPN    96

// plane sizes (elements)
#define SZ_W1 ((size_t)4096 * 1024)
#define SZ_WX ((size_t)96 * 2048)
#define SZ_WD ((size_t)2048 * 64)
#define SZ_WOT ((size_t)2048 * 1024)   // Wo transposed
#define SZ_WP ((size_t)1024 * 1024)
#define SZ_WF ((size_t)1024 * 2048)    // fused Wp@Wo
#define SZ_XT ((size_t)BL * 1024)
#define SZ_UC ((size_t)BL * 2048)
#define SZ_XD ((size_t)BL * 96)
#define SZ_Y  ((size_t)BL * 2048)

// ---------------- scratch: hi plane at [0,N), lo plane at [N,2N) ----------------
__device__ __nv_bfloat16 g_w1b[2 * SZ_W1];
__device__ __nv_bfloat16 g_wxb[2 * SZ_WX];
__device__ __nv_bfloat16 g_wdb[2 * SZ_WD];
__device__ __nv_bfloat16 g_wotb[2 * SZ_WOT];
__device__ __nv_bfloat16 g_wpb[2 * SZ_WP];
__device__ __nv_bfloat16 g_wfb[2 * SZ_WF];
__device__ __nv_bfloat16 g_xTb[2 * SZ_XT];
__device__ __nv_bfloat16 g_ucb[2 * SZ_UC];
__device__ __nv_bfloat16 g_xdb[2 * SZ_XD];
__device__ __nv_bfloat16 g_yb [2 * SZ_Y];
__device__ float g_xz   [(size_t)BL * 4096];     // u | silu(z)
__device__ float g_ucf  [(size_t)BL * 2048];
__device__ float g_xdf  [(size_t)BL * 96];
__device__ float g_delta[(size_t)BL * 2048];
__device__ float g_part [(size_t)4 * BL * XPN];  // split-K partials for x_proj

__device__ __forceinline__ float softplusf(float x) {
    return (x > 20.f) ? x : log1pf(__expf(x));
}
__device__ __forceinline__ float siluf(float x) {
    return x / (1.f + __expf(-x));
}
__device__ __forceinline__ uint32_t smem_u32(const void* p) {
    uint32_t a;
    asm("{ .reg .u64 t; cvta.to.shared.u64 t, %1; cvt.u32.u64 %0, t; }" : "=r"(a) : "l"(p));
    return a;
}

#define MMA_BF16(d, a, b0v, b1v) \
    asm volatile("mma.sync.aligned.m16n8k16.row.col.f32.bf16.bf16.f32 " \
        "{%0,%1,%2,%3}, {%4,%5,%6,%7}, {%8,%9}, {%0,%1,%2,%3};" \
        : "+f"((d)[0]), "+f"((d)[1]), "+f"((d)[2]), "+f"((d)[3]) \
        : "r"((a)[0]), "r"((a)[1]), "r"((a)[2]), "r"((a)[3]), "r"(b0v), "r"(b1v))

#define LDSM4(r, addr) \
    asm volatile("ldmatrix.sync.aligned.m8n8.x4.shared.b16 {%0,%1,%2,%3}, [%4];" \
        : "=r"((r)[0]), "=r"((r)[1]), "=r"((r)[2]), "=r"((r)[3]) : "r"(addr))

#define CP_ASYNC(dst, src) \
    asm volatile("cp.async.cg.shared.global [%0], [%1], 16;" :: "r"(dst), "l"(src) : "memory")
#define CP_ASYNC_Z(dst, src, sz) \
    asm volatile("cp.async.cg.shared.global [%0], [%1], 16, %2;" :: "r"(dst), "l"(src), "r"(sz) : "memory")
#define CP_COMMIT()  asm volatile("cp.async.commit_group;" ::: "memory")
#define CP_WAIT2()   asm volatile("cp.async.wait_group 2;" ::: "memory")
#define CP_WAIT1()   asm volatile("cp.async.wait_group 1;" ::: "memory")

// tile row: 64B, XOR swizzle on 16B chunks (conflict-free)
__device__ __forceinline__ uint32_t swz(int row, int cc) {
    uint32_t o = (uint32_t)(row * 64 + cc * 16);
    return o ^ ((((uint32_t)row >> 1) & 7u) << 4);
}

// stage layout: Ah[0,16K) Al[16K,32K) Bh[32K,40K) Bl[40K,48K)
#define STAGE_SZ 49152
#define NSTAGE   4
#define GEMM_SMEM (NSTAGE * STAGE_SZ)   // 196608

// ---------------- fp32 -> bf16 hi/lo converters ----------------
__device__ __forceinline__ void cvt_body(const float* __restrict__ s,
                                         __nv_bfloat16* __restrict__ d,
                                         size_t n, size_t i) {
    float4 v = *((const float4*)s + i);
    __nv_bfloat162 h0 = __floats2bfloat162_rn(v.x, v.y);
    __nv_bfloat162 h1 = __floats2bfloat162_rn(v.z, v.w);
    __nv_bfloat162 l0 = __floats2bfloat162_rn(v.x - __bfloat162float(h0.x),
                                              v.y - __bfloat162float(h0.y));
    __nv_bfloat162 l1 = __floats2bfloat162_rn(v.z - __bfloat162float(h1.x),
                                              v.w - __bfloat162float(h1.y));
    ((__nv_bfloat162*)d)[2 * i]     = h0;
    ((__nv_bfloat162*)d)[2 * i + 1] = h1;
    ((__nv_bfloat162*)(d + n))[2 * i]     = l0;
    ((__nv_bfloat162*)(d + n))[2 * i + 1] = l1;
}

__global__ void cvt_k(const float* __restrict__ src, __nv_bfloat16* __restrict__ db, size_t n) {
    size_t i = (size_t)blockIdx.x * 256 + threadIdx.x;
    cvt_body(src, db, n, i);
}

__global__ void cvt_rest(const float* s0, __nv_bfloat16* d0, size_t n0,
                         const float* s1, __nv_bfloat16* d1, size_t n1,
                         const float* s2, __nv_bfloat16* d2, size_t n2) {
    size_t j = (size_t)blockIdx.x * 256 + threadIdx.x;
    if (j < n0 / 4) { cvt_body(s0, d0, n0, j); return; }
    j -= n0 / 4;
    if (j < n1 / 4) { cvt_body(s1, d1, n1, j); return; }
    j -= n1 / 4;
    if (j < n2 / 4) { cvt_body(s2, d2, n2, j); return; }
}

// ---------------- x transpose -> hi/lo planes ----------------
__global__ void transpose_k(const float* __restrict__ x) {
    __shared__ float t[32][33];
    int b = blockIdx.z;
    int l0 = blockIdx.x * 32, k0 = blockIdx.y * 32;
    int tx = threadIdx.x, ty = threadIdx.y;
#pragma unroll
    for (int i = 0; i < 4; i++)
        t[ty + 8 * i][tx] = x[((size_t)(b * DMODEL + k0 + ty + 8 * i)) * LSEQ + l0 + tx];
    __syncthreads();
#pragma unroll
    for (int i = 0; i < 4; i++) {
        float v = t[tx][ty + 8 * i];
        size_t o = ((size_t)(b * LSEQ + l0 + ty + 8 * i)) * DMODEL + k0 + tx;
        __nv_bfloat16 h = __float2bfloat16(v);
        g_xTb[o] = h;
        g_xTb[SZ_XT + o] = __float2bfloat16(v - __bfloat162float(h));
    }
}

// ---------------- Wo transpose: (1024 x 2048) -> woT planes (2048 x 1024) ----------------
__global__ void txp_wo(const float* __restrict__ src) {
    __shared__ float t[32][33];
    int c0 = blockIdx.x * 32, r0 = blockIdx.y * 32;
    int tx = threadIdx.x, ty = threadIdx.y;
#pragma unroll
    for (int i = 0; i < 4; i++)
        t[ty + 8 * i][tx] = src[(size_t)(r0 + ty + 8 * i) * 2048 + c0 + tx];
    __syncthreads();
#pragma unroll
    for (int i = 0; i < 4; i++) {
        float v = t[tx][ty + 8 * i];
        size_t o = (size_t)(c0 + ty + 8 * i) * 1024 + r0 + tx;
        __nv_bfloat16 h = __float2bfloat16(v);
        g_wotb[o] = h;
        g_wotb[SZ_WOT + o] = __float2bfloat16(v - __bfloat162float(h));
    }
}

// ---------------- bf16x3 GEMM: 512 threads, 16 warps (4x4), block 256x128, warp 64x32 ----------------
// EPI: 0 fp32 (+split-K offset via blockIdx.z) | 1 softplus+bias | 2 transposed+bias
//      4 hi/lo only | 5 fp32, silu applied for cn >= DINNER (in_proj xz)
template<int EPI>
__global__ void __launch_bounds__(512, 1)
hgemm(const __nv_bfloat16* __restrict__ Ah, const __nv_bfloat16* __restrict__ Al,
      const __nv_bfloat16* __restrict__ Bh, const __nv_bfloat16* __restrict__ Bl,
      const float* __restrict__ bias, float* __restrict__ C,
      __nv_bfloat16* __restrict__ Ch, __nv_bfloat16* __restrict__ Cl,
      int M, int N, int K, int lda, int ldc)
{
    extern __shared__ char smem[];
    const uint32_t sb = smem_u32(smem);
    const int tid = threadIdx.x, lane = tid & 31, wid = tid >> 5;
    const int wm = wid >> 2, wn = wid & 3;       // 4 x 4 warp grid (rows x cols)
    const int bm = blockIdx.y * 256, bn = blockIdx.x * 128;
    const int kw = K / gridDim.z;                // split-K window
    const int kb = blockIdx.z * kw;
    const int nc = kw >> 5;

    const uint32_t akh = (uint32_t)(lane >> 4) << 4;
    uint32_t ab[4];
#pragma unroll
    for (int i = 0; i < 4; i++)
        ab[i] = swz(wm * 64 + i * 16 + (lane & 15), 0) ^ akh;
    const int brl = wn * 32 + (lane & 15);
    const uint32_t bb0 = swz(brl, 0) ^ akh;
    const uint32_t bb1 = swz(brl + 16, 0) ^ akh;

    float acc[4][4][4];
#pragma unroll
    for (int i = 0; i < 4; i++)
#pragma unroll
        for (int j = 0; j < 4; j++)
#pragma unroll
            for (int t = 0; t < 4; t++) acc[i][j][t] = 0.f;

    // ---- persistent loader state ----
    const int rq = tid >> 2;                     // 0..127
    const int cc = tid & 3;
    const uint32_t sA0 = swz(rq, cc);
    const uint32_t sA1 = swz(128 + rq, cc);
    const uint32_t sBo = swz(rq, cc);
    const int nB = bn + rq;
    const uint32_t okz = (nB < N) ? 16u : 0u;
    const __nv_bfloat16* pA0h = Ah + (size_t)(bm + rq) * lda + kb + cc * 8;
    const __nv_bfloat16* pA1h = Ah + (size_t)(bm + 128 + rq) * lda + kb + cc * 8;
    const __nv_bfloat16* pA0l = Al + (size_t)(bm + rq) * lda + kb + cc * 8;
    const __nv_bfloat16* pA1l = Al + (size_t)(bm + 128 + rq) * lda + kb + cc * 8;
    const __nv_bfloat16* pBh  = Bh + (size_t)(nB < N ? nB : 0) * K + kb + cc * 8;
    const __nv_bfloat16* pBl  = Bl + (size_t)(nB < N ? nB : 0) * K + kb + cc * 8;

    auto issue = [&](int s) {
        const uint32_t st = sb + s * STAGE_SZ;
        CP_ASYNC(st + sA0, pA0h);
        CP_ASYNC(st + sA1, pA1h);
        CP_ASYNC(st + 16384 + sA0, pA0l);
        CP_ASYNC(st + 16384 + sA1, pA1l);
        CP_ASYNC_Z(st + 32768 + sBo, pBh, okz);
        CP_ASYNC_Z(st + 40960 + sBo, pBl, okz);
        pA0h += 32; pA1h += 32; pA0l += 32; pA1l += 32;
        pBh  += 32; pBl  += 32;
    };

    issue(0); CP_COMMIT();
    if (nc > 1) issue(1);
    CP_COMMIT();
    if (nc > 2) issue(2);
    CP_COMMIT();

    for (int c = 0; c < nc; c++) {
        CP_WAIT2();
        __syncthreads();
        if (c + 3 < nc) issue((c + 3) & (NSTAGE - 1));
        CP_COMMIT();

        const uint32_t st = sb + (c & (NSTAGE - 1)) * STAGE_SZ;
#pragma unroll
        for (int ks = 0; ks < 2; ks++) {
            const uint32_t kx = (uint32_t)ks << 5;
            uint32_t ah[4][4], bh[2][4];
#pragma unroll
            for (int i = 0; i < 4; i++) LDSM4(ah[i], st + (ab[i] ^ kx));
            LDSM4(bh[0], st + 32768 + (bb0 ^ kx));
            LDSM4(bh[1], st + 32768 + (bb1 ^ kx));
#pragma unroll
            for (int i = 0; i < 4; i++) {
                MMA_BF16(acc[i][0], ah[i], bh[0][0], bh[0][2]);
                MMA_BF16(acc[i][1], ah[i], bh[0][1], bh[0][3]);
                MMA_BF16(acc[i][2], ah[i], bh[1][0], bh[1][2]);
                MMA_BF16(acc[i][3], ah[i], bh[1][1], bh[1][3]);
            }
            {
                uint32_t bl[2][4];
                LDSM4(bl[0], st + 40960 + (bb0 ^ kx));
                LDSM4(bl[1], st + 40960 + (bb1 ^ kx));
#pragma unroll
                for (int i = 0; i < 4; i++) {
                    MMA_BF16(acc[i][0], ah[i], bl[0][0], bl[0][2]);
                    MMA_BF16(acc[i][1], ah[i], bl[0][1], bl[0][3]);
                    MMA_BF16(acc[i][2], ah[i], bl[1][0], bl[1][2]);
                    MMA_BF16(acc[i][3], ah[i], bl[1][1], bl[1][3]);
                }
            }
            {
                uint32_t al[4][4];
#pragma unroll
                for (int i = 0; i < 4; i++) LDSM4(al[i], st + 16384 + (ab[i] ^ kx));
#pragma unroll
                for (int i = 0; i < 4; i++) {
                    MMA_BF16(acc[i][0], al[i], bh[0][0], bh[0][2]);
                    MMA_BF16(acc[i][1], al[i], bh[0][1], bh[0][3]);
                    MMA_BF16(acc[i][2], al[i], bh[1][0], bh[1][2]);
                    MMA_BF16(acc[i][3], al[i], bh[1][1], bh[1][3]);
                }
            }
        }
        __syncthreads();          // restored: keeps warps phase-aligned (R13 behavior)
    }

    // ---------------- epilogue ----------------
    const int lr = lane >> 2, lc = lane & 3;
#pragma unroll
    for (int i = 0; i < 4; i++) {
#pragma unroll
        for (int j = 0; j < 4; j++) {
            int r0 = bm + wm * 64 + i * 16 + lr;
            int cn = bn + wn * 32 + j * 8 + lc * 2;
            if (cn >= N) continue;
            float c0 = acc[i][j][0], c1 = acc[i][j][1];
            float c2 = acc[i][j][2], c3 = acc[i][j][3];
            if (EPI == 0) {
                float* Cz = C + (size_t)blockIdx.z * (size_t)M * ldc;
                *(float2*)&Cz[(size_t)r0 * ldc + cn]       = make_float2(c0, c1);
                *(float2*)&Cz[(size_t)(r0 + 8) * ldc + cn] = make_float2(c2, c3);
            } else if (EPI == 5) {
                if (cn >= DINNER) {
                    c0 = siluf(c0); c1 = siluf(c1);
                    c2 = siluf(c2); c3 = siluf(c3);
                }
                *(float2*)&C[(size_t)r0 * ldc + cn]       = make_float2(c0, c1);
                *(float2*)&C[(size_t)(r0 + 8) * ldc + cn] = make_float2(c2, c3);
            } else if (EPI == 1) {
                float b0 = bias[cn], b1 = bias[cn + 1];
                *(float2*)&C[(size_t)r0 * ldc + cn] =
                    make_float2(softplusf(c0 + b0), softplusf(c1 + b1));
                *(float2*)&C[(size_t)(r0 + 8) * ldc + cn] =
                    make_float2(softplusf(c2 + b0), softplusf(c3 + b1));
            } else if (EPI == 2) {
                float b0 = bias[cn], b1 = bias[cn + 1];
                int bb = r0 >> 11, l0 = r0 & (LSEQ - 1);
                size_t base0 = ((size_t)(bb * DMODEL + cn)) * LSEQ;
                C[base0 + l0]            = c0 + b0;
                C[base0 + LSEQ + l0]     = c1 + b1;
                C[base0 + l0 + 8]        = c2 + b0;
                C[base0 + LSEQ + l0 + 8] = c3 + b1;
            } else { // EPI == 4: hi/lo planes only
                __nv_bfloat162 h0 = __floats2bfloat162_rn(c0, c1);
                __nv_bfloat162 h1 = __floats2bfloat162_rn(c2, c3);
                __nv_bfloat162 l0v = __floats2bfloat162_rn(c0 - __bfloat162float(h0.x),
                                                           c1 - __bfloat162float(h0.y));
                __nv_bfloat162 l1v = __floats2bfloat162_rn(c2 - __bfloat162float(h1.x),
                                                           c3 - __bfloat162float(h1.y));
                *(__nv_bfloat162*)&Ch[(size_t)r0 * ldc + cn]       = h0;
                *(__nv_bfloat162*)&Ch[(size_t)(r0 + 8) * ldc + cn] = h1;
                *(__nv_bfloat162*)&Cl[(size_t)r0 * ldc + cn]       = l0v;
                *(__nv_bfloat162*)&Cl[(size_t)(r0 + 8) * ldc + cn] = l1v;
            }
        }
    }
}

// ---------------- split-K reduce for x_proj + hi/lo plane emit ----------------
__global__ void reduce_x() {
    size_t i = (size_t)blockIdx.x * 256 + threadIdx.x;   // < BL*XPN
    const size_t S = (size_t)BL * XPN;
    float s = g_part[i] + g_part[i + S] + g_part[i + 2 * S] + g_part[i + 3 * S];
    g_xdf[i] = s;
    __nv_bfloat16 h = __float2bfloat16(s);
    g_xdb[i] = h;
    g_xdb[SZ_XD + i] = __float2bfloat16(s - __bfloat162float(h));
}

// ---------------- depthwise causal conv + SiLU (rolling window) ----------------
__global__ void conv_silu_k(const float* __restrict__ cw, const float* __restrict__ cb) {
    int e = blockIdx.x * 256 + threadIdx.x;
    int b = blockIdx.z;
    int l0 = blockIdx.y * 128;
    float w0 = cw[e * 4], w1 = cw[e * 4 + 1], w2 = cw[e * 4 + 2], w3 = cw[e * 4 + 3];
    float bias = cb[e];
    size_t base = (size_t)b * LSEQ * 4096 + e;
    float u0 = (l0 >= 3) ? g_xz[base + (size_t)(l0 - 3) * 4096] : 0.f;
    float u1 = (l0 >= 2) ? g_xz[base + (size_t)(l0 - 2) * 4096] : 0.f;
    float u2 = (l0 >= 1) ? g_xz[base + (size_t)(l0 - 1) * 4096] : 0.f;
    for (int l = l0; l < l0 + 128; l++) {
        float u3 = g_xz[base + (size_t)l * 4096];
        float v = fmaf(w0, u0, fmaf(w1, u1, fmaf(w2, u2, fmaf(w3, u3, bias))));
        float s = siluf(v);
        size_t o = (size_t)(b * LSEQ + l) * DINNER + e;
        g_ucf[o] = s;
        __nv_bfloat16 h = __float2bfloat16(s);
        g_ucb[o] = h;
        g_ucb[SZ_UC + o] = __float2bfloat16(s - __bfloat162float(h));
        u0 = u1; u1 = u2; u2 = u3;
    }
}

// ---------------- selective scan: SMEM-staged tiles, 64 ch/block, T=64 ----------------
// stage floats: D[0,4096) U[4096,8192) Z[8192,12288) BC[12288,14336)
#define SC_T 64
#define SC_STF 14336
#define SCAN_SMEM (2 * SC_STF * 4)   // 114688 bytes

__global__ void __launch_bounds__(256, 1)
scan_k(const float* __restrict__ A_log, const float* __restrict__ Dv) {
    extern __shared__ float ss[];
    const int tid = threadIdx.x, lane = tid & 31, wid = tid >> 5;
    const int chB = blockIdx.x * 64;
    const int ch  = wid * 8 + (lane >> 2);
    const int g   = chB + ch;
    const int b   = g >> 11, d = g & (DINNER - 1);
    const int d0  = chB & (DINNER - 1);
    const int nb  = (lane & 3) * 4;
    const size_t rowbase = (size_t)b * LSEQ;
    const bool wr = ((lane & 3) == 0);

    float4 al4 = *(const float4*)&A_log[d * DSTATE + nb];
    const float Ac0 = -__expf(al4.x), Ac1 = -__expf(al4.y);
    const float Ac2 = -__expf(al4.z), Ac3 = -__expf(al4.w);
    const float Dd = Dv[d];
    float h0 = 0.f, h1 = 0.f, h2 = 0.f, h3 = 0.f;

    const uint32_t sbase = smem_u32(ss);

    auto stage_load = [&](int tile, int s) {
        const uint32_t st = sbase + (uint32_t)s * (SC_STF * 4);
        const int row0 = tile * SC_T;
#pragma unroll
        for (int i = 0; i < 4; i++) {
            int q  = tid + i * 256;
            int t  = q >> 4;
            int c4 = (q & 15) * 4;
            size_t r = rowbase + row0 + t;
            uint32_t so = (uint32_t)(t * 64 + c4) * 4;
            CP_ASYNC(st + so,          g_delta + r * DINNER + d0 + c4);
            CP_ASYNC(st + 16384 + so,  g_ucf   + r * DINNER + d0 + c4);
            CP_ASYNC(st + 32768 + so,  g_xz    + r * 4096 + DINNER + d0 + c4);
        }
#pragma unroll
        for (int i = 0; i < 2; i++) {
            int q  = tid + i * 256;
            int t  = q >> 3;
            int c4 = (q & 7) * 4;
            size_t r = rowbase + row0 + t;
            CP_ASYNC(st + 49152 + (uint32_t)(t * 32 + c4) * 4,
                     g_xdf + r * XPN + DTRANK + c4);
        }
    };

    stage_load(0, 0); CP_COMMIT();
    stage_load(1, 1); CP_COMMIT();

    const int NT = LSEQ / SC_T;
    for (int tile = 0; tile < NT; tile++) {
        CP_WAIT1();
        __syncthreads();
        const float* st = ss + (tile & 1) * SC_STF;
        const size_t rb = rowbase + (size_t)tile * SC_T;
#pragma unroll 4
        for (int t = 0; t < SC_T; t++) {
            float dval = st[t * 64 + ch];
            float uval = st[4096 + t * 64 + ch];
            float4 Bv = *(const float4*)&st[12288 + t * 32 + nb];
            float4 Cv = *(const float4*)&st[12288 + t * 32 + 16 + nb];
            float dBu = dval * uval;
            h0 = fmaf(__expf(dval * Ac0), h0, dBu * Bv.x);
            h1 = fmaf(__expf(dval * Ac1), h1, dBu * Bv.y);
            h2 = fmaf(__expf(dval * Ac2), h2, dBu * Bv.z);
            h3 = fmaf(__expf(dval * Ac3), h3, dBu * Bv.w);
            float p = fmaf(h0, Cv.x, fmaf(h1, Cv.y, fmaf(h2, Cv.z, h3 * Cv.w)));
            p += __shfl_xor_sync(0xffffffffu, p, 1);
            p += __shfl_xor_sync(0xffffffffu, p, 2);
            if (wr) {
                float zs = st[8192 + t * 64 + ch];
                float yv = (p + uval * Dd) * zs;
                size_t r = rb + t;
                __nv_bfloat16 hh = __float2bfloat16(yv);
                g_yb[r * DINNER + d] = hh;
                g_yb[SZ_Y + r * DINNER + d] = __float2bfloat16(yv - __bfloat162float(hh));
            }
        }
        __syncthreads();
        if (tile + 2 < NT) stage_load(tile + 2, tile & 1);
        CP_COMMIT();
    }
}

// ---------------- launch ----------------
extern "C" void kernel_launch(void* const* d_in, const int* in_sizes, int n_in,
                              void* d_out, int out_size)
{
    const float* x          = (const float*)d_in[0];
    const float* in_proj_w  = (const float*)d_in[1];
    const float* conv_w     = (const float*)d_in[2];
    const float* conv_b     = (const float*)d_in[3];
    const float* x_proj_w   = (const float*)d_in[4];
    const float* dt_proj_w  = (const float*)d_in[5];
    const float* dt_proj_b  = (const float*)d_in[6];
    const float* A_log      = (const float*)d_in[7];
    const float* Dv         = (const float*)d_in[8];
    const float* out_proj_w = (const float*)d_in[9];
    const float* proj_w     = (const float*)d_in[10];
    const float* proj_b     = (const float*)d_in[11];
    float* out = (float*)d_out;

    __nv_bfloat16 *w1b, *wxb, *wdb, *wotb, *wpb, *wfb, *xTb, *ucb, *xdb, *yb;
    float *xz, *ucf, *xdf, *delta, *part;
    cudaGetSymbolAddress((void**)&w1b,  g_w1b);
    cudaGetSymbolAddress((void**)&wxb,  g_wxb);
    cudaGetSymbolAddress((void**)&wdb,  g_wdb);
    cudaGetSymbolAddress((void**)&wotb, g_wotb);
    cudaGetSymbolAddress((void**)&wpb,  g_wpb);
    cudaGetSymbolAddress((void**)&wfb,  g_wfb);
    cudaGetSymbolAddress((void**)&xTb,  g_xTb);
    cudaGetSymbolAddress((void**)&ucb,  g_ucb);
    cudaGetSymbolAddress((void**)&xdb,  g_xdb);
    cudaGetSymbolAddress((void**)&yb,   g_yb);
    cudaGetSymbolAddress((void**)&xz,    g_xz);
    cudaGetSymbolAddress((void**)&ucf,   g_ucf);
    cudaGetSymbolAddress((void**)&xdf,   g_xdf);
    cudaGetSymbolAddress((void**)&delta, g_delta);
    cudaGetSymbolAddress((void**)&part,  g_part);

    cudaFuncSetAttribute(hgemm<0>, cudaFuncAttributeMaxDynamicSharedMemorySize, GEMM_SMEM);
    cudaFuncSetAttribute(hgemm<1>, cudaFuncAttributeMaxDynamicSharedMemorySize, GEMM_SMEM);
    cudaFuncSetAttribute(hgemm<2>, cudaFuncAttributeMaxDynamicSharedMemorySize, GEMM_SMEM);
    cudaFuncSetAttribute(hgemm<4>, cudaFuncAttributeMaxDynamicSharedMemorySize, GEMM_SMEM);
    cudaFuncSetAttribute(hgemm<5>, cudaFuncAttributeMaxDynamicSharedMemorySize, GEMM_SMEM);
    cudaFuncSetAttribute(scan_k,   cudaFuncAttributeMaxDynamicSharedMemorySize, SCAN_SMEM);

    // [0] in_proj weight conversion
    cvt_k<<<(int)(SZ_W1 / 1024), 256>>>(in_proj_w, w1b, SZ_W1);
    // [1] remaining weight conversions (wx, wd, wp)
    {
        size_t tot4 = (SZ_WX + SZ_WD + SZ_WP) / 4;
        cvt_rest<<<(int)((tot4 + 255) / 256), 256>>>(
            x_proj_w, wxb, SZ_WX, dt_proj_w, wdb, SZ_WD, proj_w, wpb, SZ_WP);
    }
    // [2] x transpose
    transpose_k<<<dim3(LSEQ / 32, DMODEL / 32, BQ), dim3(32, 8)>>>(x);
    // [3] in_proj: xz = xT @ W1^T (silu on z half)  <-- profiled slot
    hgemm<5><<<dim3(32, 32), 512, GEMM_SMEM>>>(xTb, xTb + SZ_XT, w1b, w1b + SZ_W1,
        nullptr, xz, nullptr, nullptr, BL, 4096, DMODEL, DMODEL, 4096);
    // [4] Wo transpose -> woT planes
    txp_wo<<<dim3(2048 / 32, 1024 / 32), dim3(32, 8)>>>(out_proj_w);
    // [5] Wf = Wp @ Wo  (1024 x 2048, K=1024) -> planes
    hgemm<4><<<dim3(16, 4), 512, GEMM_SMEM>>>(wpb, wpb + SZ_WP, wotb, wotb + SZ_WOT,
        nullptr, nullptr, wfb, wfb + SZ_WF, 1024, 2048, 1024, 1024, 2048);
    // [6] conv + silu
    conv_silu_k<<<dim3(DINNER / 256, LSEQ / 128, BQ), 256>>>(conv_w, conv_b);
    // [7] x_proj split-K=4 -> partials
    hgemm<0><<<dim3(1, 32, 4), 512, GEMM_SMEM>>>(ucb, ucb + SZ_UC, wxb, wxb + SZ_WX,
        nullptr, part, nullptr, nullptr, BL, XPN, DINNER, DINNER, XPN);
    // [8] reduce partials -> xdf + planes
    reduce_x<<<(int)((size_t)BL * XPN / 256), 256>>>();
    // [9] delta = softplus(dt_low @ Wd^T + b)
    hgemm<1><<<dim3(16, 32), 512, GEMM_SMEM>>>(xdb, xdb + SZ_XD, wdb, wdb + SZ_WD,
        dt_proj_b, delta, nullptr, nullptr, BL, DINNER, DTRANK, XPN, DINNER);
    // [10] selective scan -> y planes (SMEM-staged)
    scan_k<<<BL / 64, 256, SCAN_SMEM>>>(A_log, Dv);
    // [11] out = (y @ Wf^T + b), transposed store — replaces out_proj + proj
    hgemm<2><<<dim3(8, 32), 512, GEMM_SMEM>>>(yb, yb + SZ_Y, wfb, wfb + SZ_WF,
        proj_b, out, nullptr, nullptr, BL, DMODEL, DINNER, DINNER, 0);
}